// round 8
// baseline (speedup 1.0000x reference)
#include <cuda_runtime.h>
#include <math.h>
#include <stdint.h>

#define CS   8
#define TPB  512
#define HID  256
#define ENCL 16
#define DECL 25
#define NV   28

typedef unsigned long long ull;

// tables built by table_kernel, layout [t][unit 0..255][gate 0..3]
__device__ float g_pre[ENCL * 1024];
__device__ float g_tab[NV * 1024];

// ---------------- smem layout (float offsets) ----------------
// h ring: 3 slots x 128 entries x 16B {h_even, tag, h_odd, tag}
#define O_H3B   0               // 3*512 = 1536
#define O_CFE   1536            // cfull entries: 128 x 16B = 512
#define O_PRE   2048            // [16][32][4] = 2048
#define O_TAB   4096            // [28][32][4] = 3584
#define O_OW    7680            // out_W rows, stride 264 -> 7392
#define O_CATH  15072           // [40]
#define O_CATC  15112           // [40]
#define O_CNEW  15152           // [32]
#define O_TMP   15184           // [256] newv staging
#define O_WMAX  15440           // 2 phases x 7 ull = 28 floats
#define SMEM_FLOATS 15472
#define SMEM_BYTES  (SMEM_FLOATS * 4)

// ---------------- PTX helpers ----------------
__device__ __forceinline__ uint32_t smem_u32(const void* p) {
    uint32_t a;
    asm("{ .reg .u64 t; cvta.to.shared.u64 t, %1; cvt.u32.u64 %0, t; }" : "=r"(a) : "l"(p));
    return a;
}
__device__ __forceinline__ uint32_t mapa_u32(uint32_t a, uint32_t rank) {
    uint32_t r;
    asm("mapa.shared::cluster.u32 %0, %1, %2;" : "=r"(r) : "r"(a), "r"(rank));
    return r;
}
__device__ __forceinline__ void st_cluster_v4(uint32_t addr, uint32_t x, uint32_t y,
                                              uint32_t z, uint32_t w_) {
    asm volatile("st.shared::cluster.v4.u32 [%0], {%1,%2,%3,%4};"
                 :: "r"(addr), "r"(x), "r"(y), "r"(z), "r"(w_) : "memory");
}
__device__ __forceinline__ void cluster_bar() {
    asm volatile("barrier.cluster.arrive.aligned;" ::: "memory");
    asm volatile("barrier.cluster.wait.aligned;" ::: "memory");
}
__device__ __forceinline__ void ffma2(ull &acc, ull a, ull b) {
    asm("fma.rn.f32x2 %0, %1, %2, %0;" : "+l"(acc) : "l"(a), "l"(b));
}
__device__ __forceinline__ float ups(ull a) {
    float lo, hi;
    asm("mov.b64 {%0,%1}, %2;" : "=f"(lo), "=f"(hi) : "l"(a));
    return lo + hi;
}
__device__ __forceinline__ float sigf(float x) { return __fdividef(1.f, 1.f + __expf(-x)); }
__device__ __forceinline__ float tanhfast(float x) {
    float t = __expf(-2.f * fabsf(x));
    return copysignf(__fdividef(1.f - t, 1.f + t), x);
}
__device__ __forceinline__ float red32(float s) {
#pragma unroll
    for (int o = 16; o > 0; o >>= 1) s += __shfl_xor_sync(0xffffffffu, s, o);
    return s;
}
__device__ __forceinline__ float dot8(float4 a0, float4 a1, float4 b0, float4 b1) {
    return a0.x*b0.x + a0.y*b0.y + a0.z*b0.z + a0.w*b0.w
         + a1.x*b1.x + a1.y*b1.y + a1.z*b1.z + a1.w*b1.w;
}

// poll a 128-entry array: lane checks slice s8 (16 entries), both tag words >= n
__device__ __forceinline__ void poll_entries(uint32_t ebase, int s8, int n) {
    uint32_t sb = ebase + (uint32_t)(s8 * 256);
    for (;;) {
        int ok = 1;
#pragma unroll
        for (int j = 0; j < 16; j++) {
            uint32_t a = sb + (uint32_t)(((j + s8) & 15) << 4);
            uint32_t ex, ey, ez, ew;
            asm volatile("ld.volatile.shared.v4.u32 {%0,%1,%2,%3}, [%4];"
                         : "=r"(ex), "=r"(ey), "=r"(ez), "=r"(ew) : "r"(a) : "memory");
            ok &= ((int)ey >= n) & ((int)ew >= n);
        }
        if (__all_sync(0xffffffffu, ok)) break;
    }
}
// dual packed dot over the entry slice (weights pre-permuted to match)
__device__ __forceinline__ void dual_dot_e(const float* ebase, int s8,
                                           const ull* wA, const ull* wB,
                                           float &sA, float &sB) {
    const uint4* ep = (const uint4*)ebase;
    ull aA = 0ull, aB = 0ull;
#pragma unroll
    for (int j = 0; j < 16; j++) {
        int p = s8 * 16 + ((j + s8) & 15);
        uint4 e = ep[p];
        ull hp; asm("mov.b64 %0, {%1,%2};" : "=l"(hp) : "r"(e.x), "r"(e.z));
        ffma2(aA, wA[j], hp); ffma2(aB, wB[j], hp);
    }
    float fA = ups(aA), fB = ups(aB);
#pragma unroll
    for (int o = 1; o < 8; o <<= 1) {
        fA += __shfl_xor_sync(0xffffffffu, fA, o);
        fB += __shfl_xor_sync(0xffffffffu, fB, o);
    }
    sA = fA; sB = fB;
}
// single-row dot (smem weight row, contiguous 256 floats) over entries
__device__ __forceinline__ float one_dot_e(const float* ebase, const float* wrow, int s8) {
    const uint4* ep = (const uint4*)ebase;
    ull acc = 0ull;
#pragma unroll
    for (int j = 0; j < 16; j++) {
        int p = s8 * 16 + ((j + s8) & 15);
        uint4 e = ep[p];
        ull hp; asm("mov.b64 %0, {%1,%2};" : "=l"(hp) : "r"(e.x), "r"(e.z));
        ull wv = *(const ull*)(wrow + 2 * p);
        ffma2(acc, wv, hp);
    }
    float f = ups(acc);
#pragma unroll
    for (int o = 1; o < 8; o <<= 1) f += __shfl_xor_sync(0xffffffffu, f, o);
    return f;
}
// weights permuted to entry order: w[j] = W[R][2p..2p+1], p = s8*16+((j+s8)&15)
__device__ __forceinline__ void load_wrows_e(const float* W, int RA, int RB, int s8,
                                             ull* wA, ull* wB) {
#pragma unroll
    for (int j = 0; j < 16; j++) {
        int p = s8 * 16 + ((j + s8) & 15);
        wA[j] = *(const ull*)(W + RA * HID + 2 * p);
        wB[j] = *(const ull*)(W + RB * HID + 2 * p);
    }
}
__device__ __forceinline__ void pf_l2(const void* p) {
    asm volatile("prefetch.global.L2 [%0];" :: "l"(p));
}

// ================= kernel 1: projection tables (wide) =================
__global__ void __launch_bounds__(256) table_kernel(
    const int* data,
    const float* enc_Wih, const float* enc_bih, const float* enc_bhh, const float* enc_emb,
    const float* dec_Wih, const float* dec_bih, const float* dec_bhh, const float* dec_emb)
{
    const int tid  = threadIdx.x;
    const int w    = tid >> 5;
    const int lane = tid & 31;
    const int g    = blockIdx.x;
    const int m    = w >> 2;
    const int R    = g * 4 + (w & 3);
    const int u    = R & 255, gi = R >> 8;

    if (m == 0) {
        const float4* p = (const float4*)(enc_Wih + R * HID);
        float4 a0 = p[lane * 2], a1 = p[lane * 2 + 1];
        float bias = enc_bih[R] + enc_bhh[R];
#pragma unroll
        for (int t = 0; t < ENCL; t++) {
            const float4* x = (const float4*)(enc_emb + data[t] * HID);
            float4 x0 = x[lane * 2], x1 = x[lane * 2 + 1];
            float s = red32(dot8(a0, a1, x0, x1));
            if (lane == 0) g_pre[t * 1024 + u * 4 + gi] = s + bias;
        }
    } else {
        const float4* p = (const float4*)(dec_Wih + R * HID);
        float4 a0 = p[lane * 2], a1 = p[lane * 2 + 1];
        float bias = dec_bih[R] + dec_bhh[R];
#pragma unroll
        for (int tk = 0; tk < NV; tk++) {
            const float4* x = (const float4*)(dec_emb + tk * HID);
            float4 x0 = x[lane * 2], x1 = x[lane * 2 + 1];
            x0.x = fmaxf(x0.x, 0.f); x0.y = fmaxf(x0.y, 0.f);
            x0.z = fmaxf(x0.z, 0.f); x0.w = fmaxf(x0.w, 0.f);
            x1.x = fmaxf(x1.x, 0.f); x1.y = fmaxf(x1.y, 0.f);
            x1.z = fmaxf(x1.z, 0.f); x1.w = fmaxf(x1.w, 0.f);
            float s = red32(dot8(a0, a1, x0, x1));
            if (lane == 0) g_tab[tk * 1024 + u * 4 + gi] = s + bias;
        }
    }
}

// ================= kernel 2: single-hop fused-tag dataflow LSTM =================
__global__ void __launch_bounds__(TPB, 1) __cluster_dims__(CS, 1, 1) vae_kernel(
    const int* data_c, const int* target_c, const float* cond_emb,
    const float* enc_Whh,
    const float* hmu_W, const float* hmu_b, const float* cmu_W, const float* cmu_b,
    const float* fc1_W, const float* fc1_b, const float* fc2_W, const float* fc2_b,
    const float* dec_Whh,
    const float* out_W, const float* out_b,
    float* out, int out_size)
{
    extern __shared__ __align__(16) float sm[];
    float* pre_sh = sm + O_PRE;
    float* tab_sh = sm + O_TAB;
    float* ow_sh  = sm + O_OW;
    float* cat_h  = sm + O_CATH;
    float* cat_c  = sm + O_CATC;
    float* cnew_sh= sm + O_CNEW;
    float* tmp_sh = sm + O_TMP;
    volatile ull* wmax_sh = (volatile ull*)(sm + O_WMAX);

    const int tid  = threadIdx.x;
    const int w    = tid >> 5;
    const int lane = tid & 31;
    const int s8   = lane & 7;
    const int q    = lane >> 3;
    const int b    = blockIdx.x;
    const int sel  = lane & 1;

    const uint32_t base = smem_u32(sm);
    const uint32_t hA0  = base + O_H3B * 4;        // slot s at hA0 + s*2048

    const int RA = q * HID + b * 32 + 2 * w;       // gate q of unit 2w
    const int RB = RA + 1;

    ull wA[16], wB[16];
    load_wrows_e(enc_Whh, RA, RB, s8, wA, wB);

    uint32_t rmap[CS];
#pragma unroll
    for (int r = 0; r < CS; r++) rmap[r] = mapa_u32(base, r);

    // ---- prologue smem fills ----
    for (int i = tid; i < NV * 64; i += TPB) {
        int row = i >> 6, c4 = i & 63;
        ((float4*)(ow_sh + row * 264))[c4] = ((const float4*)out_W)[i];
    }
    for (int i = tid; i < ENCL * 32; i += TPB)
        ((float4*)pre_sh)[i] = ((const float4*)g_pre)[(i >> 5) * 256 + b * 32 + (i & 31)];
    for (int i = tid; i < NV * 32; i += TPB)
        ((float4*)tab_sh)[i] = ((const float4*)g_tab)[(i >> 5) * 256 + b * 32 + (i & 31)];
    // L2 prefetch serial-path weights
    for (int i = tid; i < 1024; i += TPB) {
        int gi = i >> 8, off = i & 255;
        pf_l2((const char*)(dec_Whh + (gi * 256 + b * 32) * HID) + off * 128);
    }
    for (int i = tid; i < 256; i += TPB) {
        pf_l2((const char*)hmu_W + i * 128);
        pf_l2((const char*)cmu_W + i * 128);
    }
    for (int i = tid; i < 320; i += TPB) {
        pf_l2((const char*)fc1_W + i * 128);
        pf_l2((const char*)fc2_W + i * 128);
    }

    const int lrow = w * 4 + q;                    // logits row for w<7
    float obv = (w < 7) ? out_b[lrow] : 0.f;

    // ---- init entries: slot0 = h0 (tag 0), slots1/2 + cfull tag 0, wmax 0 ----
    const int dcid = data_c[0], tcid = target_c[0];
    if (tid < 128) {
        int u0 = 2 * tid, u1 = u0 + 1;
        float v0 = (u0 >= HID - 8) ? cond_emb[dcid * 8 + (u0 - (HID - 8))] : 0.f;
        float v1 = (u1 >= HID - 8) ? cond_emb[dcid * 8 + (u1 - (HID - 8))] : 0.f;
        uint4* e = (uint4*)(sm + O_H3B);
        e[tid]        = make_uint4(__float_as_uint(v0), 0u, __float_as_uint(v1), 0u);
        e[128 + tid]  = make_uint4(0u, 0u, 0u, 0u);
        e[256 + tid]  = make_uint4(0u, 0u, 0u, 0u);
        ((uint4*)(sm + O_CFE))[tid] = make_uint4(0u, 0u, 0u, 0u);
    }
    if (tid < 14) ((ull*)(sm + O_WMAX))[tid] = 0ull;
    {
        int ug0 = b * 32 + 2 * w + sel;
        float creg = (ug0 >= HID - 8) ? cond_emb[dcid * 8 + (ug0 - (HID - 8))] : 0.f;

        __syncthreads();
        cluster_bar();

        // ================= encoder: steps n = 0..15 (no block barriers) =================
#pragma unroll 1
        for (int n = 0; n < ENCL; n++) {
            int slot = n % 3, slot2 = (n + 1) % 3;
            poll_entries(hA0 + (uint32_t)(slot * 2048), s8, n);
            float sA, sB;
            dual_dot_e(sm + O_H3B + slot * 512, s8, wA, wB, sA, sB);
            float a0 = __shfl_sync(0xffffffffu, sA, 0),  a1 = __shfl_sync(0xffffffffu, sA, 8);
            float a2 = __shfl_sync(0xffffffffu, sA, 16), a3 = __shfl_sync(0xffffffffu, sA, 24);
            float b0 = __shfl_sync(0xffffffffu, sB, 0),  b1 = __shfl_sync(0xffffffffu, sB, 8);
            float b2 = __shfl_sync(0xffffffffu, sB, 16), b3 = __shfl_sync(0xffffffffu, sB, 24);
            float4 pr = *(const float4*)(pre_sh + n * 128 + (2 * w + sel) * 4);
            float gi = (sel ? b0 : a0) + pr.x;
            float gf = (sel ? b1 : a1) + pr.y;
            float gg = (sel ? b2 : a2) + pr.z;
            float go = (sel ? b3 : a3) + pr.w;
            float c = sigf(gf) * creg + sigf(gi) * tanhfast(gg);
            float h = sigf(go) * tanhfast(c);
            creg = c;
            float hB = __shfl_sync(0xffffffffu, h, 1);
            float cB = __shfl_sync(0xffffffffu, c, 1);
            if (lane == 0) {
                uint32_t tg = (uint32_t)(n + 1);
                uint32_t off = (uint32_t)(O_H3B * 4 + slot2 * 2048 + (b * 16 + w) * 16);
#pragma unroll
                for (int r = 0; r < CS; r++)
                    st_cluster_v4(rmap[r] + off, __float_as_uint(h), tg, __float_as_uint(hB), tg);
                if (n == ENCL - 1) {
                    uint32_t co = (uint32_t)(O_CFE * 4 + (b * 16 + w) * 16);
#pragma unroll
                    for (int r = 0; r < CS; r++)
                        st_cluster_v4(rmap[r] + co, __float_as_uint(c), 16u, __float_as_uint(cB), 16u);
                }
            }
        }

        // hT in slot 1 (tag 16), cT in cfull (tag 16)
        poll_entries(hA0 + 2048u, s8, ENCL);
        poll_entries(base + (uint32_t)(O_CFE * 4), s8, ENCL);

        // start decoder weight reload (completes under latent math)
        load_wrows_e(dec_Whh, RA, RB, s8, wA, wB);

        // ================= latent heads + decoder init =================
        {
            const uint4* he = (const uint4*)(sm + O_H3B + 512);
            const uint4* ce = (const uint4*)(sm + O_CFE);
            uint4 e0 = he[4*lane], e1 = he[4*lane+1], e2 = he[4*lane+2], e3 = he[4*lane+3];
            float4 h0v = make_float4(__uint_as_float(e0.x), __uint_as_float(e0.z),
                                     __uint_as_float(e1.x), __uint_as_float(e1.z));
            float4 h1v = make_float4(__uint_as_float(e2.x), __uint_as_float(e2.z),
                                     __uint_as_float(e3.x), __uint_as_float(e3.z));
            e0 = ce[4*lane]; e1 = ce[4*lane+1]; e2 = ce[4*lane+2]; e3 = ce[4*lane+3];
            float4 c0v = make_float4(__uint_as_float(e0.x), __uint_as_float(e0.z),
                                     __uint_as_float(e1.x), __uint_as_float(e1.z));
            float4 c1v = make_float4(__uint_as_float(e2.x), __uint_as_float(e2.z),
                                     __uint_as_float(e3.x), __uint_as_float(e3.z));
#pragma unroll
            for (int half = 0; half < 2; half++) {
                int rr = w + half * 16;
                const float4* pp = (const float4*)(hmu_W + rr * HID);
                float4 x0 = pp[lane * 2], x1 = pp[lane * 2 + 1];
                float s = red32(dot8(x0, x1, h0v, h1v));
                if (lane == 0) cat_h[rr] = s + hmu_b[rr];
                pp = (const float4*)(cmu_W + rr * HID);
                x0 = pp[lane * 2]; x1 = pp[lane * 2 + 1];
                s = red32(dot8(x0, x1, c0v, c1v));
                if (lane == 0) cat_c[rr] = s + cmu_b[rr];
            }
        }
        if (tid < 8) {
            float v = cond_emb[tcid * 8 + tid];
            cat_h[32 + tid] = v; cat_c[32 + tid] = v;
        }
        __syncthreads();
        if (tid < HID) {
            float s = fc1_b[tid];
            const float* wr = fc1_W + tid * 40;
#pragma unroll
            for (int k = 0; k < 40; k++) s += cat_h[k] * wr[k];
            tmp_sh[tid] = s;
        }
        if (tid < 32) {
            int j = b * 32 + tid;
            float s = fc2_b[j];
            const float* wr = fc2_W + j * 40;
#pragma unroll
            for (int k = 0; k < 40; k++) s += cat_c[k] * wr[k];
            cnew_sh[tid] = s;
        }
        __syncthreads();
        if (tid < 128) {                            // dh -> slot 2 entries, tag 17
            uint4* e = (uint4*)(sm + O_H3B + 1024);
            e[tid] = make_uint4(__float_as_uint(tmp_sh[2 * tid]), 17u,
                                __float_as_uint(tmp_sh[2 * tid + 1]), 17u);
        }
        creg = cnew_sh[2 * w + sel];
        __syncthreads();

        // ================= decoder: N = 17..41 (no block barriers) =================
#pragma unroll 1
        for (int N = 17; N < 17 + DECL; N++) {
            int slot = N % 3, slot2 = (N + 1) % 3, ph = N & 1;
            poll_entries(hA0 + (uint32_t)(slot * 2048), s8, N);
            const float* ecur = sm + O_H3B + slot * 512;
            // redundant local logits of h(N) -> wmax (ranks all do this)
            if (w < 7 && N > 17) {
                float lg = one_dot_e(ecur, ow_sh + lrow * 264, s8) + obv;
                if (b == 0 && s8 == 0) out[(N - 18) * NV + lrow] = lg;
                uint32_t bits = __float_as_uint(lg);
                uint32_t key = (bits & 0x80000000u) ? ~bits : (bits | 0x80000000u);
                ull cmp = ((ull)key << 16) | ((ull)(255 - lrow) << 8) | (ull)(N & 0xff);
#pragma unroll
                for (int o = 8; o <= 16; o <<= 1) {
                    ull ot = __shfl_xor_sync(0xffffffffu, cmp, o);
                    if ((ot & 0xffff) > (cmp & 0xffff) ? false : true) { }
                    if (ot > cmp) cmp = ot;
                }
                if (lane == 0) wmax_sh[ph * 7 + w] = cmp;
            }
            float sA, sB;
            dual_dot_e(ecur, s8, wA, wB, sA, sB);
            int tok = 0;
            if (N > 17) {
                ull v;
                for (;;) {
                    v = (lane < 7) ? wmax_sh[ph * 7 + lane] : 0ull;
                    int ok = (lane < 7) ? ((int)(v & 0xffu) == (N & 0xff)) : 1;
                    if (__all_sync(0xffffffffu, ok)) break;
                }
                if (lane >= 7) v = 0ull;
#pragma unroll
                for (int o = 1; o < 32; o <<= 1) {
                    ull ot = __shfl_xor_sync(0xffffffffu, v, o);
                    if (ot > v) v = ot;
                }
                tok = 255 - (int)((v >> 8) & 0xffu);
                if (b == 0 && w == 15 && lane == 0) out[NV * DECL + (N - 18)] = (float)tok;
            }
            float a0 = __shfl_sync(0xffffffffu, sA, 0),  a1 = __shfl_sync(0xffffffffu, sA, 8);
            float a2 = __shfl_sync(0xffffffffu, sA, 16), a3 = __shfl_sync(0xffffffffu, sA, 24);
            float b0 = __shfl_sync(0xffffffffu, sB, 0),  b1 = __shfl_sync(0xffffffffu, sB, 8);
            float b2 = __shfl_sync(0xffffffffu, sB, 16), b3 = __shfl_sync(0xffffffffu, sB, 24);
            float4 pr = *(const float4*)(tab_sh + tok * 128 + (2 * w + sel) * 4);
            float gi = (sel ? b0 : a0) + pr.x;
            float gf = (sel ? b1 : a1) + pr.y;
            float gg = (sel ? b2 : a2) + pr.z;
            float go = (sel ? b3 : a3) + pr.w;
            float c = sigf(gf) * creg + sigf(gi) * tanhfast(gg);
            float h = sigf(go) * tanhfast(c);
            creg = c;
            float hB = __shfl_sync(0xffffffffu, h, 1);
            if (lane == 0) {
                uint32_t tg = (uint32_t)(N + 1);
                uint32_t off = (uint32_t)(O_H3B * 4 + slot2 * 2048 + (b * 16 + w) * 16);
#pragma unroll
                for (int r = 0; r < CS; r++)
                    st_cluster_v4(rmap[r] + off, __float_as_uint(h), tg, __float_as_uint(hB), tg);
            }
        }

        // ---- tail: logits/argmax of h(42) (slot 0, tag 42), rank 0 only ----
        if (b == 0) {
            poll_entries(hA0, s8, 42);
            if (w < 7) {
                float lg = one_dot_e(sm + O_H3B, ow_sh + lrow * 264, s8) + obv;
                if (s8 == 0) out[(DECL - 1) * NV + lrow] = lg;
                uint32_t bits = __float_as_uint(lg);
                uint32_t key = (bits & 0x80000000u) ? ~bits : (bits | 0x80000000u);
                ull cmp = ((ull)key << 16) | ((ull)(255 - lrow) << 8) | 42ull;
#pragma unroll
                for (int o = 8; o <= 16; o <<= 1) {
                    ull ot = __shfl_xor_sync(0xffffffffu, cmp, o);
                    if (ot > cmp) cmp = ot;
                }
                if (lane == 0) wmax_sh[w] = cmp;   // ph = 42&1 = 0
            }
            if (w == 15) {
                ull v;
                for (;;) {
                    v = (lane < 7) ? wmax_sh[lane] : 0ull;
                    int ok = (lane < 7) ? ((int)(v & 0xffu) == 42) : 1;
                    if (__all_sync(0xffffffffu, ok)) break;
                }
                if (lane >= 7) v = 0ull;
#pragma unroll
                for (int o = 1; o < 32; o <<= 1) {
                    ull ot = __shfl_xor_sync(0xffffffffu, v, o);
                    if (ot > v) v = ot;
                }
                if (lane == 0)
                    out[NV * DECL + (DECL - 1)] = (float)(255 - (int)((v >> 8) & 0xffu));
            }
        }
    }
    cluster_bar();
    (void)out_size;
}

extern "C" void kernel_launch(void* const* d_in, const int* in_sizes, int n_in,
                              void* d_out, int out_size) {
    (void)in_sizes; (void)n_in;
    const int*   data     = (const int*)  d_in[0];
    const int*   data_c   = (const int*)  d_in[1];
    const int*   target_c = (const int*)  d_in[2];
    const float* cond_emb = (const float*)d_in[3];
    const float* enc_emb  = (const float*)d_in[4];
    const float* enc_Wih  = (const float*)d_in[5];
    const float* enc_Whh  = (const float*)d_in[6];
    const float* enc_bih  = (const float*)d_in[7];
    const float* enc_bhh  = (const float*)d_in[8];
    const float* hmu_W    = (const float*)d_in[9];
    const float* hmu_b    = (const float*)d_in[10];
    const float* cmu_W    = (const float*)d_in[11];
    const float* cmu_b    = (const float*)d_in[12];
    const float* fc1_W    = (const float*)d_in[13];
    const float* fc1_b    = (const float*)d_in[14];
    const float* fc2_W    = (const float*)d_in[15];
    const float* fc2_b    = (const float*)d_in[16];
    const float* dec_emb  = (const float*)d_in[17];
    const float* dec_Wih  = (const float*)d_in[18];
    const float* dec_Whh  = (const float*)d_in[19];
    const float* dec_bih  = (const float*)d_in[20];
    const float* dec_bhh  = (const float*)d_in[21];
    const float* out_W    = (const float*)d_in[22];
    const float* out_b    = (const float*)d_in[23];

    table_kernel<<<256, 256>>>(data, enc_Wih, enc_bih, enc_bhh, enc_emb,
                               dec_Wih, dec_bih, dec_bhh, dec_emb);

    cudaFuncSetAttribute(vae_kernel, cudaFuncAttributeMaxDynamicSharedMemorySize, SMEM_BYTES);
    vae_kernel<<<CS, TPB, SMEM_BYTES>>>(data_c, target_c, cond_emb,
                                        enc_Whh,
                                        hmu_W, hmu_b, cmu_W, cmu_b,
                                        fc1_W, fc1_b, fc2_W, fc2_b,
                                        dec_Whh,
                                        out_W, out_b,
                                        (float*)d_out, out_size);
}

// round 9
// speedup vs baseline: 1.4620x; 1.4620x over previous
#include <cuda_runtime.h>
#include <math.h>
#include <stdint.h>

#define CS   8
#define TPB  512
#define HID  256
#define ENCL 16
#define DECL 25
#define NV   28

typedef unsigned long long ull;
#define FULLM 0xffffffffu

// tables built by table_kernel, layout [t][unit 0..255][gate 0..3]
__device__ float g_pre[ENCL * 1024];
__device__ float g_tab[NV * 1024];

// ---------------- smem layout (float offsets) ----------------
#define O_H3B   0               // 3 x 256 h ring
#define O_CF    768             // cfull [256]
#define O_PRE   1024            // [16][32 units][4 gates] = 2048
#define O_TAB   3072            // [28][32][4] = 3584
#define O_CATH  6656            // [40]
#define O_CATC  6696            // [40]
#define O_CNEW  6736            // [32]
#define O_WMAX  6768            // 2 phases x 16 ull = 64 floats
#define SMEM_FLOATS 6832
#define SMEM_BYTES  (SMEM_FLOATS * 4)

// ---------------- PTX helpers ----------------
__device__ __forceinline__ uint32_t smem_u32(const void* p) {
    uint32_t a;
    asm("{ .reg .u64 t; cvta.to.shared.u64 t, %1; cvt.u32.u64 %0, t; }" : "=r"(a) : "l"(p));
    return a;
}
__device__ __forceinline__ uint32_t mapa_u32(uint32_t a, uint32_t rank) {
    uint32_t r;
    asm("mapa.shared::cluster.u32 %0, %1, %2;" : "=r"(r) : "r"(a), "r"(rank));
    return r;
}
__device__ __forceinline__ void st_cluster_b64(uint32_t addr, ull v) {
    asm volatile("st.shared::cluster.b64 [%0], %1;" :: "r"(addr), "l"(v) : "memory");
}
__device__ __forceinline__ void cluster_bar() {
    asm volatile("barrier.cluster.arrive.aligned;" ::: "memory");
    asm volatile("barrier.cluster.wait.aligned;" ::: "memory");
}
__device__ __forceinline__ void ffma2(ull &acc, ull a, ull b) {
    asm("fma.rn.f32x2 %0, %1, %2, %0;" : "+l"(acc) : "l"(a), "l"(b));
}
__device__ __forceinline__ float ups(ull a) {
    float lo, hi;
    asm("mov.b64 {%0,%1}, %2;" : "=f"(lo), "=f"(hi) : "l"(a));
    return lo + hi;
}
__device__ __forceinline__ ull pack2(float lo, float hi) {
    ull r;
    asm("mov.b64 %0, {%1,%2};" : "=l"(r) : "f"(lo), "f"(hi));
    return r;
}
__device__ __forceinline__ float sigf(float x) { return __fdividef(1.f, 1.f + __expf(-x)); }
__device__ __forceinline__ float tanhfast(float x) {
    float t = __expf(-2.f * fabsf(x));
    return copysignf(__fdividef(1.f - t, 1.f + t), x);
}
__device__ __forceinline__ float red32(float s) {
#pragma unroll
    for (int o = 16; o > 0; o >>= 1) s += __shfl_xor_sync(FULLM, s, o);
    return s;
}
__device__ __forceinline__ float dot8(float4 a0, float4 a1, float4 b0, float4 b1) {
    return a0.x*b0.x + a0.y*b0.y + a0.z*b0.z + a0.w*b0.w
         + a1.x*b1.x + a1.y*b1.y + a1.z*b1.z + a1.w*b1.w;
}
__device__ __forceinline__ void pf_l2(const void* p) {
    asm volatile("prefetch.global.L2 [%0];" :: "l"(p));
}

// 8 gate-row weight chunks (lane's 8 h-elems) for this warp
__device__ __forceinline__ void load_w8(const float* W, int b, int w, int lane, ull wr[8][4]) {
#pragma unroll
    for (int r = 0; r < 8; r++) {
        int row = (r & 3) * HID + b * 32 + 2 * w + (r >> 2);
        const ulonglong2* p = (const ulonglong2*)(W + row * HID + 8 * lane);
        ulonglong2 v0 = p[0], v1 = p[1];
        wr[r][0] = v0.x; wr[r][1] = v0.y; wr[r][2] = v1.x; wr[r][3] = v1.y;
    }
}

// multi-acc butterfly: 8 partials/lane -> every lane holds total of acc (lane&7)
__device__ __forceinline__ float reduce8(float a0, float a1, float a2, float a3,
                                         float a4, float a5, float a6, float a7, int lane) {
    a0 += __shfl_xor_sync(FULLM, a0, 16); a1 += __shfl_xor_sync(FULLM, a1, 16);
    a2 += __shfl_xor_sync(FULLM, a2, 16); a3 += __shfl_xor_sync(FULLM, a3, 16);
    a4 += __shfl_xor_sync(FULLM, a4, 16); a5 += __shfl_xor_sync(FULLM, a5, 16);
    a6 += __shfl_xor_sync(FULLM, a6, 16); a7 += __shfl_xor_sync(FULLM, a7, 16);
    a0 += __shfl_xor_sync(FULLM, a0, 8);  a1 += __shfl_xor_sync(FULLM, a1, 8);
    a2 += __shfl_xor_sync(FULLM, a2, 8);  a3 += __shfl_xor_sync(FULLM, a3, 8);
    a4 += __shfl_xor_sync(FULLM, a4, 8);  a5 += __shfl_xor_sync(FULLM, a5, 8);
    a6 += __shfl_xor_sync(FULLM, a6, 8);  a7 += __shfl_xor_sync(FULLM, a7, 8);
    bool b2 = (lane >> 2) & 1;
    float s0 = b2 ? a0 : a4, s1 = b2 ? a1 : a5, s2 = b2 ? a2 : a6, s3 = b2 ? a3 : a7;
    float r0 = __shfl_xor_sync(FULLM, s0, 4), r1 = __shfl_xor_sync(FULLM, s1, 4);
    float r2 = __shfl_xor_sync(FULLM, s2, 4), r3 = __shfl_xor_sync(FULLM, s3, 4);
    float k0 = (b2 ? a4 : a0) + r0, k1 = (b2 ? a5 : a1) + r1;
    float k2 = (b2 ? a6 : a2) + r2, k3 = (b2 ? a7 : a3) + r3;
    bool b1 = (lane >> 1) & 1;
    float t0 = b1 ? k0 : k2, t1 = b1 ? k1 : k3;
    float u0 = __shfl_xor_sync(FULLM, t0, 2), u1 = __shfl_xor_sync(FULLM, t1, 2);
    float m0 = (b1 ? k2 : k0) + u0, m1 = (b1 ? k3 : k1) + u1;
    bool b0 = lane & 1;
    float sv = b0 ? m0 : m1;
    float rv = __shfl_xor_sync(FULLM, sv, 1);
    return (b0 ? m1 : m0) + rv;
}
// 2-acc reduce: every lane gets total of acc (lane&1)
__device__ __forceinline__ float reduce2(float l0, float l1, int lane) {
    l0 += __shfl_xor_sync(FULLM, l0, 16); l1 += __shfl_xor_sync(FULLM, l1, 16);
    l0 += __shfl_xor_sync(FULLM, l0, 8);  l1 += __shfl_xor_sync(FULLM, l1, 8);
    l0 += __shfl_xor_sync(FULLM, l0, 4);  l1 += __shfl_xor_sync(FULLM, l1, 4);
    l0 += __shfl_xor_sync(FULLM, l0, 2);  l1 += __shfl_xor_sync(FULLM, l1, 2);
    bool b0 = lane & 1;
    float s = b0 ? l0 : l1;
    float r = __shfl_xor_sync(FULLM, s, 1);
    return (b0 ? l1 : l0) + r;
}

// ================= kernel 1: projection tables (wide) =================
__global__ void __launch_bounds__(256) table_kernel(
    const int* data,
    const float* enc_Wih, const float* enc_bih, const float* enc_bhh, const float* enc_emb,
    const float* dec_Wih, const float* dec_bih, const float* dec_bhh, const float* dec_emb)
{
    const int tid  = threadIdx.x;
    const int w    = tid >> 5;
    const int lane = tid & 31;
    const int g    = blockIdx.x;
    const int m    = w >> 2;
    const int R    = g * 4 + (w & 3);
    const int u    = R & 255, gi = R >> 8;

    if (m == 0) {
        const float4* p = (const float4*)(enc_Wih + R * HID);
        float4 a0 = p[lane * 2], a1 = p[lane * 2 + 1];
        float bias = enc_bih[R] + enc_bhh[R];
#pragma unroll
        for (int t = 0; t < ENCL; t++) {
            const float4* x = (const float4*)(enc_emb + data[t] * HID);
            float4 x0 = x[lane * 2], x1 = x[lane * 2 + 1];
            float s = red32(dot8(a0, a1, x0, x1));
            if (lane == 0) g_pre[t * 1024 + u * 4 + gi] = s + bias;
        }
    } else {
        const float4* p = (const float4*)(dec_Wih + R * HID);
        float4 a0 = p[lane * 2], a1 = p[lane * 2 + 1];
        float bias = dec_bih[R] + dec_bhh[R];
#pragma unroll
        for (int tk = 0; tk < NV; tk++) {
            const float4* x = (const float4*)(dec_emb + tk * HID);
            float4 x0 = x[lane * 2], x1 = x[lane * 2 + 1];
            x0.x = fmaxf(x0.x, 0.f); x0.y = fmaxf(x0.y, 0.f);
            x0.z = fmaxf(x0.z, 0.f); x0.w = fmaxf(x0.w, 0.f);
            x1.x = fmaxf(x1.x, 0.f); x1.y = fmaxf(x1.y, 0.f);
            x1.z = fmaxf(x1.z, 0.f); x1.w = fmaxf(x1.w, 0.f);
            float s = red32(dot8(a0, a1, x0, x1));
            if (lane == 0) g_tab[tk * 1024 + u * 4 + gi] = s + bias;
        }
    }
}

// ================= kernel 2: lean-crossbar LSTM =================
__global__ void __launch_bounds__(TPB, 1) __cluster_dims__(CS, 1, 1) vae_kernel(
    const int* data_c, const int* target_c, const float* cond_emb,
    const float* enc_Whh,
    const float* hmu_W, const float* hmu_b, const float* cmu_W, const float* cmu_b,
    const float* fc1_W, const float* fc1_b, const float* fc2_W, const float* fc2_b,
    const float* dec_Whh,
    const float* out_W, const float* out_b,
    float* out, int out_size)
{
    extern __shared__ __align__(16) float sm[];
    float* h3b    = sm + O_H3B;
    float* cfull  = sm + O_CF;
    float* pre_sh = sm + O_PRE;
    float* tab_sh = sm + O_TAB;
    float* cat_h  = sm + O_CATH;
    float* cat_c  = sm + O_CATC;
    float* cnew_sh= sm + O_CNEW;
    volatile ull* wmax_sh = (volatile ull*)(sm + O_WMAX);

    const int tid  = threadIdx.x;
    const int w    = tid >> 5;
    const int lane = tid & 31;
    const int b    = blockIdx.x;
    const int uu   = (lane >> 2) & 1;       // unit mirror within warp (valid lanes 0..7)

    const uint32_t base = smem_u32(sm);

    // recurrent weights (encoder first; decoder reloads same regs)
    ull wr[8][4];
    load_w8(enc_Whh, b, w, lane, wr);

    uint32_t rmap[CS];
#pragma unroll
    for (int r = 0; r < CS; r++) rmap[r] = mapa_u32(base, r);

    // ---- prologue smem fills ----
    for (int i = tid; i < ENCL * 32; i += TPB)
        ((float4*)pre_sh)[i] = ((const float4*)g_pre)[(i >> 5) * 256 + b * 32 + (i & 31)];
    for (int i = tid; i < NV * 32; i += TPB)
        ((float4*)tab_sh)[i] = ((const float4*)g_tab)[(i >> 5) * 256 + b * 32 + (i & 31)];
    // L2 prefetch serial-path weights
    for (int i = tid; i < 1024; i += TPB) {
        int gi = i >> 8, off = i & 255;
        pf_l2((const char*)(dec_Whh + (gi * 256 + b * 32) * HID) + off * 128);
    }
    for (int i = tid; i < 256; i += TPB) {
        pf_l2((const char*)hmu_W + i * 128);
        pf_l2((const char*)cmu_W + i * 128);
    }
    for (int i = tid; i < 320; i += TPB) {
        pf_l2((const char*)fc1_W + i * 128);
        pf_l2((const char*)fc2_W + i * 128);
    }
    for (int i = tid; i < 224; i += TPB)
        pf_l2((const char*)out_W + i * 128);

    // ---- h0 (slot 0) + c0 ----
    const int dcid = data_c[0], tcid = target_c[0];
    if (tid < HID) {
        float v = (tid >= HID - 8) ? cond_emb[dcid * 8 + (tid - (HID - 8))] : 0.f;
        h3b[tid] = v;
    }
    int ug = b * 32 + 2 * w + uu;
    float creg = (ug >= HID - 8) ? cond_emb[dcid * 8 + (ug - (HID - 8))] : 0.f;

    __syncthreads();
    cluster_bar();

    // ================= encoder: n = 0..15 (no __syncthreads) =================
#pragma unroll 1
    for (int n = 0; n < ENCL; n++) {
        int slot = n % 3, slot2 = (n + 1) % 3;
        const ulonglong2* hp = (const ulonglong2*)(h3b + slot * HID);
        ulonglong2 X = hp[lane * 2], Y = hp[lane * 2 + 1];
        float a[8];
#pragma unroll
        for (int r = 0; r < 8; r++) {
            ull ac = 0ull;
            ffma2(ac, wr[r][0], X.x); ffma2(ac, wr[r][1], X.y);
            ffma2(ac, wr[r][2], Y.x); ffma2(ac, wr[r][3], Y.y);
            a[r] = ups(ac);
        }
        float tot = reduce8(a[0], a[1], a[2], a[3], a[4], a[5], a[6], a[7], lane);
        int gb = lane & 28;
        float g0 = __shfl_sync(FULLM, tot, gb);
        float g1 = __shfl_sync(FULLM, tot, gb | 1);
        float g2 = __shfl_sync(FULLM, tot, gb | 2);
        float g3 = __shfl_sync(FULLM, tot, gb | 3);
        float4 pr = *(const float4*)(pre_sh + n * 128 + (2 * w + uu) * 4);
        float gi = g0 + pr.x, gf = g1 + pr.y, gg = g2 + pr.z, go = g3 + pr.w;
        float c = sigf(gf) * creg + sigf(gi) * tanhfast(gg);
        float h = sigf(go) * tanhfast(c);
        creg = c;
        float hB = __shfl_sync(FULLM, h, 4);
        if (lane == 0) {
            ull hp2 = pack2(h, hB);
            uint32_t off = (uint32_t)((slot2 * HID + b * 32 + 2 * w) * 4);
#pragma unroll
            for (int r = 0; r < CS; r++) st_cluster_b64(rmap[r] + off, hp2);
        }
        if (n == ENCL - 1) {
            float cB = __shfl_sync(FULLM, c, 4);
            if (lane == 0) {
                ull cp = pack2(c, cB);
                uint32_t co = (uint32_t)((O_CF + b * 32 + 2 * w) * 4);
#pragma unroll
                for (int r = 0; r < CS; r++) st_cluster_b64(rmap[r] + co, cp);
            }
        }
        cluster_bar();
    }

    // hT in slot 1, cT in cfull (released by last bar)

    // ================= latent heads + decoder init (redundant per CTA) =================
    {
        const float4* hv = (const float4*)(h3b + HID) + lane * 2;
        float4 h0v = hv[0], h1v = hv[1];
        const float4* cv = (const float4*)cfull + lane * 2;
        float4 c0v = cv[0], c1v = cv[1];
#pragma unroll
        for (int half = 0; half < 2; half++) {
            int rr = w + half * 16;
            const float4* pp = (const float4*)(hmu_W + rr * HID);
            float4 x0 = pp[lane * 2], x1 = pp[lane * 2 + 1];
            float s = red32(dot8(x0, x1, h0v, h1v));
            if (lane == 0) cat_h[rr] = s + hmu_b[rr];
            pp = (const float4*)(cmu_W + rr * HID);
            x0 = pp[lane * 2]; x1 = pp[lane * 2 + 1];
            s = red32(dot8(x0, x1, c0v, c1v));
            if (lane == 0) cat_c[rr] = s + cmu_b[rr];
        }
    }
    if (tid < 8) {
        float v = cond_emb[tcid * 8 + tid];
        cat_h[32 + tid] = v; cat_c[32 + tid] = v;
    }
    __syncthreads();
    float newv = 0.f;
    if (tid < HID) {
        float s = fc1_b[tid];
        const float* wrp = fc1_W + tid * 40;
#pragma unroll
        for (int k = 0; k < 40; k++) s += cat_h[k] * wrp[k];
        newv = s;
    }
    if (tid < 32) {
        int j = b * 32 + tid;
        float s = fc2_b[j];
        const float* wrp = fc2_W + j * 40;
#pragma unroll
        for (int k = 0; k < 40; k++) s += cat_c[k] * wrp[k];
        cnew_sh[tid] = s;
    }
    __syncthreads();
    if (tid < HID) h3b[2 * HID + tid] = newv;           // dh -> slot 2 (= h(17))
    creg = cnew_sh[2 * w + uu];

    // decoder weights + out_W rows (2 per warp, w<14) into registers
    load_w8(dec_Whh, b, w, lane, wr);
    ull owr[2][4];
    {
        int lw = (w < 14) ? w : 0;
#pragma unroll
        for (int rr = 0; rr < 2; rr++) {
            const ulonglong2* p = (const ulonglong2*)(out_W + (2 * lw + rr) * HID + 8 * lane);
            ulonglong2 v0 = p[0], v1 = p[1];
            owr[rr][0] = v0.x; owr[rr][1] = v0.y; owr[rr][2] = v1.x; owr[rr][3] = v1.y;
        }
    }
    float obv = (w < 14) ? out_b[2 * w + (lane & 1)] : 0.f;
    __syncthreads();

    // ================= decoder: N = 17..41 =================
#pragma unroll 1
    for (int N = 17; N < 17 + DECL; N++) {
        int slot = N % 3, slot2 = (N + 1) % 3, ph = N & 1;
        const ulonglong2* hp = (const ulonglong2*)(h3b + slot * HID);
        ulonglong2 X = hp[lane * 2], Y = hp[lane * 2 + 1];

        // logits of h(N) (output index N-18), rows 2w, 2w+1 for w<14
        float lgv = 0.f;
        if (w < 14 && N > 17) {
            ull la0 = 0ull, la1 = 0ull;
            ffma2(la0, owr[0][0], X.x); ffma2(la0, owr[0][1], X.y);
            ffma2(la0, owr[0][2], Y.x); ffma2(la0, owr[0][3], Y.y);
            ffma2(la1, owr[1][0], X.x); ffma2(la1, owr[1][1], X.y);
            ffma2(la1, owr[1][2], Y.x); ffma2(la1, owr[1][3], Y.y);
            lgv = reduce2(ups(la0), ups(la1), lane) + obv;   // lane&1 -> row 2w+(lane&1)
            uint32_t bits = __float_as_uint(lgv);
            uint32_t key = (bits & 0x80000000u) ? ~bits : (bits | 0x80000000u);
            int row = 2 * w + (lane & 1);
            ull cmp = ((ull)key << 8) | (ull)(255 - row);
            ull c1 = __shfl_xor_sync(FULLM, cmp, 1);
            if (c1 > cmp) cmp = c1;
            if (lane == 0) wmax_sh[ph * 16 + w] = cmp;
        }

        float a[8];
#pragma unroll
        for (int r = 0; r < 8; r++) {
            ull ac = 0ull;
            ffma2(ac, wr[r][0], X.x); ffma2(ac, wr[r][1], X.y);
            ffma2(ac, wr[r][2], Y.x); ffma2(ac, wr[r][3], Y.y);
            a[r] = ups(ac);
        }
        float tot = reduce8(a[0], a[1], a[2], a[3], a[4], a[5], a[6], a[7], lane);

        __syncthreads();                                    // wmax visible

        int tok = 0;
        if (N > 17) {
            ull v = (lane < 14) ? wmax_sh[ph * 16 + lane] : 0ull;
#pragma unroll
            for (int o = 1; o < 32; o <<= 1) {
                ull ot = __shfl_xor_sync(FULLM, v, o);
                if (ot > v) v = ot;
            }
            tok = 255 - (int)(v & 0xffu);
            if (b == 0) {
                if (w < 14 && lane < 2) out[(N - 18) * NV + 2 * w + lane] = lgv;
                if (w == 15 && lane == 0) out[NV * DECL + (N - 18)] = (float)tok;
            }
        }

        int gb = lane & 28;
        float g0 = __shfl_sync(FULLM, tot, gb);
        float g1 = __shfl_sync(FULLM, tot, gb | 1);
        float g2 = __shfl_sync(FULLM, tot, gb | 2);
        float g3 = __shfl_sync(FULLM, tot, gb | 3);
        float4 pr = *(const float4*)(tab_sh + tok * 128 + (2 * w + uu) * 4);
        float gi = g0 + pr.x, gf = g1 + pr.y, gg = g2 + pr.z, go = g3 + pr.w;
        float c = sigf(gf) * creg + sigf(gi) * tanhfast(gg);
        float h = sigf(go) * tanhfast(c);
        creg = c;
        float hB = __shfl_sync(FULLM, h, 4);
        if (lane == 0) {
            ull hp2 = pack2(h, hB);
            uint32_t off = (uint32_t)((slot2 * HID + b * 32 + 2 * w) * 4);
#pragma unroll
            for (int r = 0; r < CS; r++) st_cluster_b64(rmap[r] + off, hp2);
        }
        cluster_bar();
    }

    // ---- tail: logits/argmax of h(42) (slot 0) ----
    if (b == 0) {
        const ulonglong2* hp = (const ulonglong2*)h3b;
        ulonglong2 X = hp[lane * 2], Y = hp[lane * 2 + 1];
        float lgv = 0.f;
        if (w < 14) {
            ull la0 = 0ull, la1 = 0ull;
            ffma2(la0, owr[0][0], X.x); ffma2(la0, owr[0][1], X.y);
            ffma2(la0, owr[0][2], Y.x); ffma2(la0, owr[0][3], Y.y);
            ffma2(la1, owr[1][0], X.x); ffma2(la1, owr[1][1], X.y);
            ffma2(la1, owr[1][2], Y.x); ffma2(la1, owr[1][3], Y.y);
            lgv = reduce2(ups(la0), ups(la1), lane) + obv;
            uint32_t bits = __float_as_uint(lgv);
            uint32_t key = (bits & 0x80000000u) ? ~bits : (bits | 0x80000000u);
            int row = 2 * w + (lane & 1);
            ull cmp = ((ull)key << 8) | (ull)(255 - row);
            ull c1 = __shfl_xor_sync(FULLM, cmp, 1);
            if (c1 > cmp) cmp = c1;
            if (lane == 0) wmax_sh[w] = cmp;                 // ph slot 0
            if (lane < 2) out[(DECL - 1) * NV + row] = lgv;
        }
        __syncthreads();
        if (w == 15) {
            ull v = (lane < 14) ? wmax_sh[lane] : 0ull;
#pragma unroll
            for (int o = 1; o < 32; o <<= 1) {
                ull ot = __shfl_xor_sync(FULLM, v, o);
                if (ot > v) v = ot;
            }
            if (lane == 0)
                out[NV * DECL + (DECL - 1)] = (float)(255 - (int)(v & 0xffu));
        }
    }
    cluster_bar();
    (void)out_size; (void)ug;
}

extern "C" void kernel_launch(void* const* d_in, const int* in_sizes, int n_in,
                              void* d_out, int out_size) {
    (void)in_sizes; (void)n_in;
    const int*   data     = (const int*)  d_in[0];
    const int*   data_c   = (const int*)  d_in[1];
    const int*   target_c = (const int*)  d_in[2];
    const float* cond_emb = (const float*)d_in[3];
    const float* enc_emb  = (const float*)d_in[4];
    const float* enc_Wih  = (const float*)d_in[5];
    const float* enc_Whh  = (const float*)d_in[6];
    const float* enc_bih  = (const float*)d_in[7];
    const float* enc_bhh  = (const float*)d_in[8];
    const float* hmu_W    = (const float*)d_in[9];
    const float* hmu_b    = (const float*)d_in[10];
    const float* cmu_W    = (const float*)d_in[11];
    const float* cmu_b    = (const float*)d_in[12];
    const float* fc1_W    = (const float*)d_in[13];
    const float* fc1_b    = (const float*)d_in[14];
    const float* fc2_W    = (const float*)d_in[15];
    const float* fc2_b    = (const float*)d_in[16];
    const float* dec_emb  = (const float*)d_in[17];
    const float* dec_Wih  = (const float*)d_in[18];
    const float* dec_Whh  = (const float*)d_in[19];
    const float* dec_bih  = (const float*)d_in[20];
    const float* dec_bhh  = (const float*)d_in[21];
    const float* out_W    = (const float*)d_in[22];
    const float* out_b    = (const float*)d_in[23];

    table_kernel<<<256, 256>>>(data, enc_Wih, enc_bih, enc_bhh, enc_emb,
                               dec_Wih, dec_bih, dec_bhh, dec_emb);

    cudaFuncSetAttribute(vae_kernel, cudaFuncAttributeMaxDynamicSharedMemorySize, SMEM_BYTES);
    vae_kernel<<<CS, TPB, SMEM_BYTES>>>(data_c, target_c, cond_emb,
                                        enc_Whh,
                                        hmu_W, hmu_b, cmu_W, cmu_b,
                                        fc1_W, fc1_b, fc2_W, fc2_b,
                                        dec_Whh,
                                        out_W, out_b,
                                        (float*)d_out, out_size);
}

// round 10
// speedup vs baseline: 1.4696x; 1.0052x over previous
#include <cuda_runtime.h>
#include <math.h>
#include <stdint.h>

#define CS   8
#define TPB  512
#define HID  256
#define ENCL 16
#define DECL 25
#define NV   28

typedef unsigned long long ull;
#define FULLM 0xffffffffu

// tables built by table_kernel, layout [t][unit 0..255][gate 0..3]
__device__ float g_pre[ENCL * 1024];
__device__ float g_tab[NV * 1024];
__device__ int   g_flag[128];        // [0..63] enc done per table-CTA, [64..127] dec done

// ---------------- smem layout (float offsets) ----------------
#define O_H3B   0               // 3 x 256 h ring
#define O_CF    768             // cfull [256]
#define O_PRE   1024            // [16][32 units][4 gates] = 2048
#define O_TAB   3072            // [28][32][4] = 3584
#define O_CATH  6656            // [40]
#define O_CATC  6696            // [40]
#define O_CNEW  6736            // [32]
#define O_WMAX  6768            // 2 phases x 16 ull = 64 floats
#define SMEM_FLOATS 6832
#define SMEM_BYTES  (SMEM_FLOATS * 4)

// ---------------- PTX helpers ----------------
__device__ __forceinline__ uint32_t smem_u32(const void* p) {
    uint32_t a;
    asm("{ .reg .u64 t; cvta.to.shared.u64 t, %1; cvt.u32.u64 %0, t; }" : "=r"(a) : "l"(p));
    return a;
}
__device__ __forceinline__ uint32_t mapa_u32(uint32_t a, uint32_t rank) {
    uint32_t r;
    asm("mapa.shared::cluster.u32 %0, %1, %2;" : "=r"(r) : "r"(a), "r"(rank));
    return r;
}
__device__ __forceinline__ void st_cluster_b64(uint32_t addr, ull v) {
    asm volatile("st.shared::cluster.b64 [%0], %1;" :: "r"(addr), "l"(v) : "memory");
}
__device__ __forceinline__ void cluster_bar() {
    asm volatile("barrier.cluster.arrive.aligned;" ::: "memory");
    asm volatile("barrier.cluster.wait.aligned;" ::: "memory");
}
__device__ __forceinline__ int ld_acq_gpu(const int* p) {
    int v;
    asm volatile("ld.acquire.gpu.global.s32 %0, [%1];" : "=r"(v) : "l"(p) : "memory");
    return v;
}
__device__ __forceinline__ void st_rel_gpu(int* p, int v) {
    asm volatile("st.release.gpu.global.s32 [%0], %1;" :: "l"(p), "r"(v) : "memory");
}
__device__ __forceinline__ void ffma2(ull &acc, ull a, ull b) {
    asm("fma.rn.f32x2 %0, %1, %2, %0;" : "+l"(acc) : "l"(a), "l"(b));
}
__device__ __forceinline__ float ups(ull a) {
    float lo, hi;
    asm("mov.b64 {%0,%1}, %2;" : "=f"(lo), "=f"(hi) : "l"(a));
    return lo + hi;
}
__device__ __forceinline__ ull pack2(float lo, float hi) {
    ull r;
    asm("mov.b64 %0, {%1,%2};" : "=l"(r) : "f"(lo), "f"(hi));
    return r;
}
__device__ __forceinline__ float sigf(float x) { return __fdividef(1.f, 1.f + __expf(-x)); }
__device__ __forceinline__ float tanhfast(float x) {
    float t = __expf(-2.f * fabsf(x));
    return copysignf(__fdividef(1.f - t, 1.f + t), x);
}
__device__ __forceinline__ float red32(float s) {
#pragma unroll
    for (int o = 16; o > 0; o >>= 1) s += __shfl_xor_sync(FULLM, s, o);
    return s;
}
__device__ __forceinline__ float dot8(float4 a0, float4 a1, float4 b0, float4 b1) {
    return a0.x*b0.x + a0.y*b0.y + a0.z*b0.z + a0.w*b0.w
         + a1.x*b1.x + a1.y*b1.y + a1.z*b1.z + a1.w*b1.w;
}
__device__ __forceinline__ void pf_l2(const void* p) {
    asm volatile("prefetch.global.L2 [%0];" :: "l"(p));
}

// 8 gate-row weight chunks (lane's 8 h-elems) for this warp
__device__ __forceinline__ void load_w8(const float* W, int b, int w, int lane, ull wr[8][4]) {
#pragma unroll
    for (int r = 0; r < 8; r++) {
        int row = (r & 3) * HID + b * 32 + 2 * w + (r >> 2);
        const ulonglong2* p = (const ulonglong2*)(W + row * HID + 8 * lane);
        ulonglong2 v0 = p[0], v1 = p[1];
        wr[r][0] = v0.x; wr[r][1] = v0.y; wr[r][2] = v1.x; wr[r][3] = v1.y;
    }
}

// multi-acc butterfly: 8 partials/lane -> every lane holds total of acc (lane&7)
__device__ __forceinline__ float reduce8(float a0, float a1, float a2, float a3,
                                         float a4, float a5, float a6, float a7, int lane) {
    a0 += __shfl_xor_sync(FULLM, a0, 16); a1 += __shfl_xor_sync(FULLM, a1, 16);
    a2 += __shfl_xor_sync(FULLM, a2, 16); a3 += __shfl_xor_sync(FULLM, a3, 16);
    a4 += __shfl_xor_sync(FULLM, a4, 16); a5 += __shfl_xor_sync(FULLM, a5, 16);
    a6 += __shfl_xor_sync(FULLM, a6, 16); a7 += __shfl_xor_sync(FULLM, a7, 16);
    a0 += __shfl_xor_sync(FULLM, a0, 8);  a1 += __shfl_xor_sync(FULLM, a1, 8);
    a2 += __shfl_xor_sync(FULLM, a2, 8);  a3 += __shfl_xor_sync(FULLM, a3, 8);
    a4 += __shfl_xor_sync(FULLM, a4, 8);  a5 += __shfl_xor_sync(FULLM, a5, 8);
    a6 += __shfl_xor_sync(FULLM, a6, 8);  a7 += __shfl_xor_sync(FULLM, a7, 8);
    bool b2 = (lane >> 2) & 1;
    float s0 = b2 ? a0 : a4, s1 = b2 ? a1 : a5, s2 = b2 ? a2 : a6, s3 = b2 ? a3 : a7;
    float r0 = __shfl_xor_sync(FULLM, s0, 4), r1 = __shfl_xor_sync(FULLM, s1, 4);
    float r2 = __shfl_xor_sync(FULLM, s2, 4), r3 = __shfl_xor_sync(FULLM, s3, 4);
    float k0 = (b2 ? a4 : a0) + r0, k1 = (b2 ? a5 : a1) + r1;
    float k2 = (b2 ? a6 : a2) + r2, k3 = (b2 ? a7 : a3) + r3;
    bool b1 = (lane >> 1) & 1;
    float t0 = b1 ? k0 : k2, t1 = b1 ? k1 : k3;
    float u0 = __shfl_xor_sync(FULLM, t0, 2), u1 = __shfl_xor_sync(FULLM, t1, 2);
    float m0 = (b1 ? k2 : k0) + u0, m1 = (b1 ? k3 : k1) + u1;
    bool b0 = lane & 1;
    float sv = b0 ? m0 : m1;
    float rv = __shfl_xor_sync(FULLM, sv, 1);
    return (b0 ? m1 : m0) + rv;
}
// 2-acc reduce: every lane gets total of acc (lane&1)
__device__ __forceinline__ float reduce2(float l0, float l1, int lane) {
    l0 += __shfl_xor_sync(FULLM, l0, 16); l1 += __shfl_xor_sync(FULLM, l1, 16);
    l0 += __shfl_xor_sync(FULLM, l0, 8);  l1 += __shfl_xor_sync(FULLM, l1, 8);
    l0 += __shfl_xor_sync(FULLM, l0, 4);  l1 += __shfl_xor_sync(FULLM, l1, 4);
    l0 += __shfl_xor_sync(FULLM, l0, 2);  l1 += __shfl_xor_sync(FULLM, l1, 2);
    bool b0 = lane & 1;
    float s = b0 ? l0 : l1;
    float r = __shfl_xor_sync(FULLM, s, 1);
    return (b0 ? l1 : l0) + r;
}

// ================= kernel 1: projection tables (64 CTAs, flagged) =================
__global__ void __launch_bounds__(256) table_kernel(
    const int* data,
    const float* enc_Wih, const float* enc_bih, const float* enc_bhh, const float* enc_emb,
    const float* dec_Wih, const float* dec_bih, const float* dec_bhh, const float* dec_emb)
{
    __shared__ __align__(16) float xs[NV * HID];     // 28 KB staging
    const int tid  = threadIdx.x;
    const int w    = tid >> 5;
    const int lane = tid & 31;
    const int g    = blockIdx.x;                     // 0..63
    const int R0   = g * 16 + 2 * w;                 // rows R0, R0+1
    const int R1   = R0 + 1;
    const int u0   = R0 & 255, g0 = R0 >> 8;
    const int u1   = R1 & 255, g1 = R1 >> 8;

    // ---- encoder half ----
    for (int i = tid; i < ENCL * 64; i += 256) {
        int t = i >> 6, c4 = i & 63;
        ((float4*)xs)[i] = ((const float4*)(enc_emb + data[t] * HID))[c4];
    }
    __syncthreads();
    {
        const float4* p0 = (const float4*)(enc_Wih + R0 * HID);
        const float4* p1 = (const float4*)(enc_Wih + R1 * HID);
        float4 a00 = p0[lane * 2], a01 = p0[lane * 2 + 1];
        float4 a10 = p1[lane * 2], a11 = p1[lane * 2 + 1];
        float bias0 = enc_bih[R0] + enc_bhh[R0];
        float bias1 = enc_bih[R1] + enc_bhh[R1];
#pragma unroll 1
        for (int t = 0; t < ENCL; t++) {
            const float4* xv = (const float4*)(xs + t * HID) + lane * 2;
            float4 x0 = xv[0], x1 = xv[1];
            float s0 = red32(dot8(a00, a01, x0, x1));
            float s1 = red32(dot8(a10, a11, x0, x1));
            if (lane == 0) {
                g_pre[t * 1024 + u0 * 4 + g0] = s0 + bias0;
                g_pre[t * 1024 + u1 * 4 + g1] = s1 + bias1;
            }
        }
    }
    __syncthreads();
    if (tid == 0) st_rel_gpu(&g_flag[g], 1);

    // ---- decoder half ----
    for (int i = tid; i < NV * 64; i += 256) {
        int tk = i >> 6, c4 = i & 63;
        float4 v = ((const float4*)(dec_emb + tk * HID))[c4];
        v.x = fmaxf(v.x, 0.f); v.y = fmaxf(v.y, 0.f);
        v.z = fmaxf(v.z, 0.f); v.w = fmaxf(v.w, 0.f);
        ((float4*)xs)[i] = v;
    }
    __syncthreads();
    {
        const float4* p0 = (const float4*)(dec_Wih + R0 * HID);
        const float4* p1 = (const float4*)(dec_Wih + R1 * HID);
        float4 a00 = p0[lane * 2], a01 = p0[lane * 2 + 1];
        float4 a10 = p1[lane * 2], a11 = p1[lane * 2 + 1];
        float bias0 = dec_bih[R0] + dec_bhh[R0];
        float bias1 = dec_bih[R1] + dec_bhh[R1];
#pragma unroll 1
        for (int tk = 0; tk < NV; tk++) {
            const float4* xv = (const float4*)(xs + tk * HID) + lane * 2;
            float4 x0 = xv[0], x1 = xv[1];
            float s0 = red32(dot8(a00, a01, x0, x1));
            float s1 = red32(dot8(a10, a11, x0, x1));
            if (lane == 0) {
                g_tab[tk * 1024 + u0 * 4 + g0] = s0 + bias0;
                g_tab[tk * 1024 + u1 * 4 + g1] = s1 + bias1;
            }
        }
    }
    __syncthreads();
    if (tid == 0) st_rel_gpu(&g_flag[64 + g], 1);
}

// ================= kernel 2: lean-crossbar LSTM (R9 body + flag waits) =================
__global__ void __launch_bounds__(TPB, 1) __cluster_dims__(CS, 1, 1) vae_kernel(
    const int* data_c, const int* target_c, const float* cond_emb,
    const float* enc_Whh,
    const float* hmu_W, const float* hmu_b, const float* cmu_W, const float* cmu_b,
    const float* fc1_W, const float* fc1_b, const float* fc2_W, const float* fc2_b,
    const float* dec_Whh,
    const float* out_W, const float* out_b,
    float* out, int out_size)
{
    extern __shared__ __align__(16) float sm[];
    float* h3b    = sm + O_H3B;
    float* cfull  = sm + O_CF;
    float* pre_sh = sm + O_PRE;
    float* tab_sh = sm + O_TAB;
    float* cat_h  = sm + O_CATH;
    float* cat_c  = sm + O_CATC;
    float* cnew_sh= sm + O_CNEW;
    volatile ull* wmax_sh = (volatile ull*)(sm + O_WMAX);

    const int tid  = threadIdx.x;
    const int w    = tid >> 5;
    const int lane = tid & 31;
    const int b    = blockIdx.x;
    const int uu   = (lane >> 2) & 1;

    const uint32_t base = smem_u32(sm);

    ull wr[8][4];
    load_w8(enc_Whh, b, w, lane, wr);

    uint32_t rmap[CS];
#pragma unroll
    for (int r = 0; r < CS; r++) rmap[r] = mapa_u32(base, r);

    // L2 prefetch serial-path weights (while table kernel runs elsewhere)
    for (int i = tid; i < 1024; i += TPB) {
        int gi = i >> 8, off = i & 255;
        pf_l2((const char*)(dec_Whh + (gi * 256 + b * 32) * HID) + off * 128);
    }
    for (int i = tid; i < 256; i += TPB) {
        pf_l2((const char*)hmu_W + i * 128);
        pf_l2((const char*)cmu_W + i * 128);
    }
    for (int i = tid; i < 320; i += TPB) {
        pf_l2((const char*)fc1_W + i * 128);
        pf_l2((const char*)fc2_W + i * 128);
    }
    for (int i = tid; i < 224; i += TPB)
        pf_l2((const char*)out_W + i * 128);

    // ---- h0 (slot 0) + c0 ----
    const int dcid = data_c[0], tcid = target_c[0];
    if (tid < HID) {
        float v = (tid >= HID - 8) ? cond_emb[dcid * 8 + (tid - (HID - 8))] : 0.f;
        h3b[tid] = v;
    }
    int ug = b * 32 + 2 * w + uu;
    float creg = (ug >= HID - 8) ? cond_emb[dcid * 8 + (ug - (HID - 8))] : 0.f;

    // wait for encoder tables (concurrent table kernel), then copy slice
    if (tid < 64) while (ld_acq_gpu(&g_flag[tid]) == 0) { }
    __syncthreads();
    for (int i = tid; i < ENCL * 32; i += TPB)
        ((float4*)pre_sh)[i] = ((const float4*)g_pre)[(i >> 5) * 256 + b * 32 + (i & 31)];

    __syncthreads();
    cluster_bar();

    // ================= encoder: n = 0..15 =================
#pragma unroll 1
    for (int n = 0; n < ENCL; n++) {
        int slot = n % 3, slot2 = (n + 1) % 3;
        const ulonglong2* hp = (const ulonglong2*)(h3b + slot * HID);
        ulonglong2 X = hp[lane * 2], Y = hp[lane * 2 + 1];
        float a[8];
#pragma unroll
        for (int r = 0; r < 8; r++) {
            ull ac = 0ull;
            ffma2(ac, wr[r][0], X.x); ffma2(ac, wr[r][1], X.y);
            ffma2(ac, wr[r][2], Y.x); ffma2(ac, wr[r][3], Y.y);
            a[r] = ups(ac);
        }
        float tot = reduce8(a[0], a[1], a[2], a[3], a[4], a[5], a[6], a[7], lane);
        int gb = lane & 28;
        float g0 = __shfl_sync(FULLM, tot, gb);
        float g1 = __shfl_sync(FULLM, tot, gb | 1);
        float g2 = __shfl_sync(FULLM, tot, gb | 2);
        float g3 = __shfl_sync(FULLM, tot, gb | 3);
        float4 pr = *(const float4*)(pre_sh + n * 128 + (2 * w + uu) * 4);
        float gi = g0 + pr.x, gf = g1 + pr.y, gg = g2 + pr.z, go = g3 + pr.w;
        float c = sigf(gf) * creg + sigf(gi) * tanhfast(gg);
        float h = sigf(go) * tanhfast(c);
        creg = c;
        float hB = __shfl_sync(FULLM, h, 4);
        if (lane == 0) {
            ull hp2 = pack2(h, hB);
            uint32_t off = (uint32_t)((slot2 * HID + b * 32 + 2 * w) * 4);
#pragma unroll
            for (int r = 0; r < CS; r++) st_cluster_b64(rmap[r] + off, hp2);
        }
        if (n == ENCL - 1) {
            float cB = __shfl_sync(FULLM, c, 4);
            if (lane == 0) {
                ull cp = pack2(c, cB);
                uint32_t co = (uint32_t)((O_CF + b * 32 + 2 * w) * 4);
#pragma unroll
                for (int r = 0; r < CS; r++) st_cluster_b64(rmap[r] + co, cp);
            }
        }
        cluster_bar();
    }

    // ================= latent heads + decoder init (redundant per CTA) =================
    {
        const float4* hv = (const float4*)(h3b + HID) + lane * 2;
        float4 h0v = hv[0], h1v = hv[1];
        const float4* cv = (const float4*)cfull + lane * 2;
        float4 c0v = cv[0], c1v = cv[1];
#pragma unroll
        for (int half = 0; half < 2; half++) {
            int rr = w + half * 16;
            const float4* pp = (const float4*)(hmu_W + rr * HID);
            float4 x0 = pp[lane * 2], x1 = pp[lane * 2 + 1];
            float s = red32(dot8(x0, x1, h0v, h1v));
            if (lane == 0) cat_h[rr] = s + hmu_b[rr];
            pp = (const float4*)(cmu_W + rr * HID);
            x0 = pp[lane * 2]; x1 = pp[lane * 2 + 1];
            s = red32(dot8(x0, x1, c0v, c1v));
            if (lane == 0) cat_c[rr] = s + cmu_b[rr];
        }
    }
    if (tid < 8) {
        float v = cond_emb[tcid * 8 + tid];
        cat_h[32 + tid] = v; cat_c[32 + tid] = v;
    }
    __syncthreads();
    float newv = 0.f;
    if (tid < HID) {
        float s = fc1_b[tid];
        const float* wrp = fc1_W + tid * 40;
#pragma unroll
        for (int k = 0; k < 40; k++) s += cat_h[k] * wrp[k];
        newv = s;
    }
    if (tid < 32) {
        int j = b * 32 + tid;
        float s = fc2_b[j];
        const float* wrp = fc2_W + j * 40;
#pragma unroll
        for (int k = 0; k < 40; k++) s += cat_c[k] * wrp[k];
        cnew_sh[tid] = s;
    }
    __syncthreads();
    if (tid < HID) h3b[2 * HID + tid] = newv;           // dh -> slot 2 (= h(17))
    creg = cnew_sh[2 * w + uu];

    // decoder token table (flags long since set; copy now)
    if (tid < 64) while (ld_acq_gpu(&g_flag[64 + tid]) == 0) { }
    __syncthreads();
    for (int i = tid; i < NV * 32; i += TPB)
        ((float4*)tab_sh)[i] = ((const float4*)g_tab)[(i >> 5) * 256 + b * 32 + (i & 31)];

    // decoder weights + out_W rows (2 per warp, w<14) into registers
    load_w8(dec_Whh, b, w, lane, wr);
    ull owr[2][4];
    {
        int lw = (w < 14) ? w : 0;
#pragma unroll
        for (int rr = 0; rr < 2; rr++) {
            const ulonglong2* p = (const ulonglong2*)(out_W + (2 * lw + rr) * HID + 8 * lane);
            ulonglong2 v0 = p[0], v1 = p[1];
            owr[rr][0] = v0.x; owr[rr][1] = v0.y; owr[rr][2] = v1.x; owr[rr][3] = v1.y;
        }
    }
    float obv = (w < 14) ? out_b[2 * w + (lane & 1)] : 0.f;
    __syncthreads();

    // ================= decoder: N = 17..41 =================
#pragma unroll 1
    for (int N = 17; N < 17 + DECL; N++) {
        int slot = N % 3, slot2 = (N + 1) % 3, ph = N & 1;
        const ulonglong2* hp = (const ulonglong2*)(h3b + slot * HID);
        ulonglong2 X = hp[lane * 2], Y = hp[lane * 2 + 1];

        float lgv = 0.f;
        if (w < 14 && N > 17) {
            ull la0 = 0ull, la1 = 0ull;
            ffma2(la0, owr[0][0], X.x); ffma2(la0, owr[0][1], X.y);
            ffma2(la0, owr[0][2], Y.x); ffma2(la0, owr[0][3], Y.y);
            ffma2(la1, owr[1][0], X.x); ffma2(la1, owr[1][1], X.y);
            ffma2(la1, owr[1][2], Y.x); ffma2(la1, owr[1][3], Y.y);
            lgv = reduce2(ups(la0), ups(la1), lane) + obv;
            uint32_t bits = __float_as_uint(lgv);
            uint32_t key = (bits & 0x80000000u) ? ~bits : (bits | 0x80000000u);
            int row = 2 * w + (lane & 1);
            ull cmp = ((ull)key << 8) | (ull)(255 - row);
            ull c1 = __shfl_xor_sync(FULLM, cmp, 1);
            if (c1 > cmp) cmp = c1;
            if (lane == 0) wmax_sh[ph * 16 + w] = cmp;
        }

        float a[8];
#pragma unroll
        for (int r = 0; r < 8; r++) {
            ull ac = 0ull;
            ffma2(ac, wr[r][0], X.x); ffma2(ac, wr[r][1], X.y);
            ffma2(ac, wr[r][2], Y.x); ffma2(ac, wr[r][3], Y.y);
            a[r] = ups(ac);
        }
        float tot = reduce8(a[0], a[1], a[2], a[3], a[4], a[5], a[6], a[7], lane);

        __syncthreads();

        int tok = 0;
        if (N > 17) {
            ull v = (lane < 14) ? wmax_sh[ph * 16 + lane] : 0ull;
#pragma unroll
            for (int o = 1; o < 32; o <<= 1) {
                ull ot = __shfl_xor_sync(FULLM, v, o);
                if (ot > v) v = ot;
            }
            tok = 255 - (int)(v & 0xffu);
            if (b == 0) {
                if (w < 14 && lane < 2) out[(N - 18) * NV + 2 * w + lane] = lgv;
                if (w == 15 && lane == 0) out[NV * DECL + (N - 18)] = (float)tok;
            }
        }

        int gb = lane & 28;
        float g0 = __shfl_sync(FULLM, tot, gb);
        float g1 = __shfl_sync(FULLM, tot, gb | 1);
        float g2 = __shfl_sync(FULLM, tot, gb | 2);
        float g3 = __shfl_sync(FULLM, tot, gb | 3);
        float4 pr = *(const float4*)(tab_sh + tok * 128 + (2 * w + uu) * 4);
        float gi = g0 + pr.x, gf = g1 + pr.y, gg = g2 + pr.z, go = g3 + pr.w;
        float c = sigf(gf) * creg + sigf(gi) * tanhfast(gg);
        float h = sigf(go) * tanhfast(c);
        creg = c;
        float hB = __shfl_sync(FULLM, h, 4);
        if (lane == 0) {
            ull hp2 = pack2(h, hB);
            uint32_t off = (uint32_t)((slot2 * HID + b * 32 + 2 * w) * 4);
#pragma unroll
            for (int r = 0; r < CS; r++) st_cluster_b64(rmap[r] + off, hp2);
        }
        cluster_bar();
    }

    // ---- tail: logits/argmax of h(42) (slot 0) ----
    if (b == 0) {
        const ulonglong2* hp = (const ulonglong2*)h3b;
        ulonglong2 X = hp[lane * 2], Y = hp[lane * 2 + 1];
        float lgv = 0.f;
        if (w < 14) {
            ull la0 = 0ull, la1 = 0ull;
            ffma2(la0, owr[0][0], X.x); ffma2(la0, owr[0][1], X.y);
            ffma2(la0, owr[0][2], Y.x); ffma2(la0, owr[0][3], Y.y);
            ffma2(la1, owr[1][0], X.x); ffma2(la1, owr[1][1], X.y);
            ffma2(la1, owr[1][2], Y.x); ffma2(la1, owr[1][3], Y.y);
            lgv = reduce2(ups(la0), ups(la1), lane) + obv;
            uint32_t bits = __float_as_uint(lgv);
            uint32_t key = (bits & 0x80000000u) ? ~bits : (bits | 0x80000000u);
            int row = 2 * w + (lane & 1);
            ull cmp = ((ull)key << 8) | (ull)(255 - row);
            ull c1 = __shfl_xor_sync(FULLM, cmp, 1);
            if (c1 > cmp) cmp = c1;
            if (lane == 0) wmax_sh[w] = cmp;
            if (lane < 2) out[(DECL - 1) * NV + row] = lgv;
        }
        __syncthreads();
        if (w == 15) {
            ull v = (lane < 14) ? wmax_sh[lane] : 0ull;
#pragma unroll
            for (int o = 1; o < 32; o <<= 1) {
                ull ot = __shfl_xor_sync(FULLM, v, o);
                if (ot > v) v = ot;
            }
            if (lane == 0)
                out[NV * DECL + (DECL - 1)] = (float)(255 - (int)(v & 0xffu));
        }
        // reset flags for the next graph replay (replays serialize, so safe)
        if (tid < 128) g_flag[tid] = 0;
    }
    cluster_bar();
    (void)out_size; (void)ug;
}

// host-side fork/join resources (created once, on the uncaptured correctness call)
struct HxCtx {
    cudaStream_t s2;
    cudaEvent_t  eF, eJ;
    HxCtx() {
        cudaStreamCreateWithFlags(&s2, cudaStreamNonBlocking);
        cudaEventCreateWithFlags(&eF, cudaEventDisableTiming);
        cudaEventCreateWithFlags(&eJ, cudaEventDisableTiming);
    }
};
static HxCtx& hx_ctx() { static HxCtx c; return c; }

extern "C" void kernel_launch(void* const* d_in, const int* in_sizes, int n_in,
                              void* d_out, int out_size) {
    (void)in_sizes; (void)n_in;
    const int*   data     = (const int*)  d_in[0];
    const int*   data_c   = (const int*)  d_in[1];
    const int*   target_c = (const int*)  d_in[2];
    const float* cond_emb = (const float*)d_in[3];
    const float* enc_emb  = (const float*)d_in[4];
    const float* enc_Wih  = (const float*)d_in[5];
    const float* enc_Whh  = (const float*)d_in[6];
    const float* enc_bih  = (const float*)d_in[7];
    const float* enc_bhh  = (const float*)d_in[8];
    const float* hmu_W    = (const float*)d_in[9];
    const float* hmu_b    = (const float*)d_in[10];
    const float* cmu_W    = (const float*)d_in[11];
    const float* cmu_b    = (const float*)d_in[12];
    const float* fc1_W    = (const float*)d_in[13];
    const float* fc1_b    = (const float*)d_in[14];
    const float* fc2_W    = (const float*)d_in[15];
    const float* fc2_b    = (const float*)d_in[16];
    const float* dec_emb  = (const float*)d_in[17];
    const float* dec_Wih  = (const float*)d_in[18];
    const float* dec_Whh  = (const float*)d_in[19];
    const float* dec_bih  = (const float*)d_in[20];
    const float* dec_bhh  = (const float*)d_in[21];
    const float* out_W    = (const float*)d_in[22];
    const float* out_b    = (const float*)d_in[23];

    HxCtx& c = hx_ctx();

    // fork: table kernel runs concurrently with vae_kernel; join after both
    cudaEventRecord(c.eF, 0);
    cudaStreamWaitEvent(c.s2, c.eF, 0);
    table_kernel<<<64, 256, 0, c.s2>>>(data, enc_Wih, enc_bih, enc_bhh, enc_emb,
                                       dec_Wih, dec_bih, dec_bhh, dec_emb);
    cudaEventRecord(c.eJ, c.s2);

    cudaFuncSetAttribute(vae_kernel, cudaFuncAttributeMaxDynamicSharedMemorySize, SMEM_BYTES);
    vae_kernel<<<CS, TPB, SMEM_BYTES>>>(data_c, target_c, cond_emb,
                                        enc_Whh,
                                        hmu_W, hmu_b, cmu_W, cmu_b,
                                        fc1_W, fc1_b, fc2_W, fc2_b,
                                        dec_Whh,
                                        out_W, out_b,
                                        (float*)d_out, out_size);
    cudaStreamWaitEvent(0, c.eJ, 0);
}

// round 11
// speedup vs baseline: 1.5088x; 1.0267x over previous
#include <cuda_runtime.h>
#include <math.h>
#include <stdint.h>

#define CS   8
#define TPB  512
#define HID  256
#define ENCL 16
#define DECL 25
#define NV   28

typedef unsigned long long ull;
#define FULLM 0xffffffffu

// dec projection table built by dec_table_kernel, layout [tok][unit 0..255][gate 0..3]
__device__ float g_tab[NV * 1024];
__device__ int   g_flag[64];         // dec done per table-CTA; reset each run

// ---------------- smem layout (float offsets) ----------------
#define O_H3B   0               // 3 x 256 h ring
#define O_CF    768             // cfull [256]
#define O_PRE   1024            // [16][32 units][4 gates] = 2048
#define O_TAB   3072            // [28][32][4] = 3584
#define O_CATH  6656            // [40]
#define O_CATC  6696            // [40]
#define O_CNEW  6736            // [32]
#define O_WMAX  6768            // 2 phases x 16 ull = 64 floats
#define O_XS    6832            // enc_emb staging [16][256] = 4096
#define SMEM_FLOATS 10928
#define SMEM_BYTES  (SMEM_FLOATS * 4)

// ---------------- PTX helpers ----------------
__device__ __forceinline__ uint32_t smem_u32(const void* p) {
    uint32_t a;
    asm("{ .reg .u64 t; cvta.to.shared.u64 t, %1; cvt.u32.u64 %0, t; }" : "=r"(a) : "l"(p));
    return a;
}
__device__ __forceinline__ uint32_t mapa_u32(uint32_t a, uint32_t rank) {
    uint32_t r;
    asm("mapa.shared::cluster.u32 %0, %1, %2;" : "=r"(r) : "r"(a), "r"(rank));
    return r;
}
__device__ __forceinline__ void st_cluster_b64(uint32_t addr, ull v) {
    asm volatile("st.shared::cluster.b64 [%0], %1;" :: "r"(addr), "l"(v) : "memory");
}
__device__ __forceinline__ void cluster_bar() {
    asm volatile("barrier.cluster.arrive.aligned;" ::: "memory");
    asm volatile("barrier.cluster.wait.aligned;" ::: "memory");
}
__device__ __forceinline__ int ld_acq_gpu(const int* p) {
    int v;
    asm volatile("ld.acquire.gpu.global.s32 %0, [%1];" : "=r"(v) : "l"(p) : "memory");
    return v;
}
__device__ __forceinline__ void st_rel_gpu(int* p, int v) {
    asm volatile("st.release.gpu.global.s32 [%0], %1;" :: "l"(p), "r"(v) : "memory");
}
__device__ __forceinline__ void ffma2(ull &acc, ull a, ull b) {
    asm("fma.rn.f32x2 %0, %1, %2, %0;" : "+l"(acc) : "l"(a), "l"(b));
}
__device__ __forceinline__ float ups(ull a) {
    float lo, hi;
    asm("mov.b64 {%0,%1}, %2;" : "=f"(lo), "=f"(hi) : "l"(a));
    return lo + hi;
}
__device__ __forceinline__ ull pack2(float lo, float hi) {
    ull r;
    asm("mov.b64 %0, {%1,%2};" : "=l"(r) : "f"(lo), "f"(hi));
    return r;
}
__device__ __forceinline__ float sigf(float x) { return __fdividef(1.f, 1.f + __expf(-x)); }
__device__ __forceinline__ float tanhfast(float x) {
    float t = __expf(-2.f * fabsf(x));
    return copysignf(__fdividef(1.f - t, 1.f + t), x);
}
__device__ __forceinline__ float red32(float s) {
#pragma unroll
    for (int o = 16; o > 0; o >>= 1) s += __shfl_xor_sync(FULLM, s, o);
    return s;
}
__device__ __forceinline__ float dot8(float4 a0, float4 a1, float4 b0, float4 b1) {
    return a0.x*b0.x + a0.y*b0.y + a0.z*b0.z + a0.w*b0.w
         + a1.x*b1.x + a1.y*b1.y + a1.z*b1.z + a1.w*b1.w;
}
__device__ __forceinline__ void pf_l2(const void* p) {
    asm volatile("prefetch.global.L2 [%0];" :: "l"(p));
}

// 8 gate-row weight chunks (lane's 8 h-elems) for this warp
__device__ __forceinline__ void load_w8(const float* W, int b, int w, int lane, ull wr[8][4]) {
#pragma unroll
    for (int r = 0; r < 8; r++) {
        int row = (r & 3) * HID + b * 32 + 2 * w + (r >> 2);
        const ulonglong2* p = (const ulonglong2*)(W + row * HID + 8 * lane);
        ulonglong2 v0 = p[0], v1 = p[1];
        wr[r][0] = v0.x; wr[r][1] = v0.y; wr[r][2] = v1.x; wr[r][3] = v1.y;
    }
}

// multi-acc butterfly: 8 partials/lane -> every lane holds total of acc (lane&7)
__device__ __forceinline__ float reduce8(float a0, float a1, float a2, float a3,
                                         float a4, float a5, float a6, float a7, int lane) {
    a0 += __shfl_xor_sync(FULLM, a0, 16); a1 += __shfl_xor_sync(FULLM, a1, 16);
    a2 += __shfl_xor_sync(FULLM, a2, 16); a3 += __shfl_xor_sync(FULLM, a3, 16);
    a4 += __shfl_xor_sync(FULLM, a4, 16); a5 += __shfl_xor_sync(FULLM, a5, 16);
    a6 += __shfl_xor_sync(FULLM, a6, 16); a7 += __shfl_xor_sync(FULLM, a7, 16);
    a0 += __shfl_xor_sync(FULLM, a0, 8);  a1 += __shfl_xor_sync(FULLM, a1, 8);
    a2 += __shfl_xor_sync(FULLM, a2, 8);  a3 += __shfl_xor_sync(FULLM, a3, 8);
    a4 += __shfl_xor_sync(FULLM, a4, 8);  a5 += __shfl_xor_sync(FULLM, a5, 8);
    a6 += __shfl_xor_sync(FULLM, a6, 8);  a7 += __shfl_xor_sync(FULLM, a7, 8);
    bool b2 = (lane >> 2) & 1;
    float s0 = b2 ? a0 : a4, s1 = b2 ? a1 : a5, s2 = b2 ? a2 : a6, s3 = b2 ? a3 : a7;
    float r0 = __shfl_xor_sync(FULLM, s0, 4), r1 = __shfl_xor_sync(FULLM, s1, 4);
    float r2 = __shfl_xor_sync(FULLM, s2, 4), r3 = __shfl_xor_sync(FULLM, s3, 4);
    float k0 = (b2 ? a4 : a0) + r0, k1 = (b2 ? a5 : a1) + r1;
    float k2 = (b2 ? a6 : a2) + r2, k3 = (b2 ? a7 : a3) + r3;
    bool b1 = (lane >> 1) & 1;
    float t0 = b1 ? k0 : k2, t1 = b1 ? k1 : k3;
    float u0 = __shfl_xor_sync(FULLM, t0, 2), u1 = __shfl_xor_sync(FULLM, t1, 2);
    float m0 = (b1 ? k2 : k0) + u0, m1 = (b1 ? k3 : k1) + u1;
    bool b0 = lane & 1;
    float sv = b0 ? m0 : m1;
    float rv = __shfl_xor_sync(FULLM, sv, 1);
    return (b0 ? m1 : m0) + rv;
}
// 2-acc reduce: every lane gets total of acc (lane&1)
__device__ __forceinline__ float reduce2(float l0, float l1, int lane) {
    l0 += __shfl_xor_sync(FULLM, l0, 16); l1 += __shfl_xor_sync(FULLM, l1, 16);
    l0 += __shfl_xor_sync(FULLM, l0, 8);  l1 += __shfl_xor_sync(FULLM, l1, 8);
    l0 += __shfl_xor_sync(FULLM, l0, 4);  l1 += __shfl_xor_sync(FULLM, l1, 4);
    l0 += __shfl_xor_sync(FULLM, l0, 2);  l1 += __shfl_xor_sync(FULLM, l1, 2);
    bool b0 = lane & 1;
    float s = b0 ? l0 : l1;
    float r = __shfl_xor_sync(FULLM, s, 1);
    return (b0 ? l1 : l0) + r;
}

// ================= kernel 1: DEC projection table only (forked, overlapped) =================
__global__ void __launch_bounds__(256) dec_table_kernel(
    const float* dec_Wih, const float* dec_bih, const float* dec_bhh, const float* dec_emb)
{
    __shared__ __align__(16) float xs[NV * HID];     // 28 KB staging
    const int tid  = threadIdx.x;
    const int w    = tid >> 5;
    const int lane = tid & 31;
    const int g    = blockIdx.x;                     // 0..63
    const int R0   = g * 16 + 2 * w;
    const int R1   = R0 + 1;
    const int u0   = R0 & 255, g0 = R0 >> 8;
    const int u1   = R1 & 255, g1 = R1 >> 8;

    for (int i = tid; i < NV * 64; i += 256) {
        int tk = i >> 6, c4 = i & 63;
        float4 v = ((const float4*)(dec_emb + tk * HID))[c4];
        v.x = fmaxf(v.x, 0.f); v.y = fmaxf(v.y, 0.f);
        v.z = fmaxf(v.z, 0.f); v.w = fmaxf(v.w, 0.f);
        ((float4*)xs)[i] = v;
    }
    __syncthreads();
    const float4* p0 = (const float4*)(dec_Wih + R0 * HID);
    const float4* p1 = (const float4*)(dec_Wih + R1 * HID);
    float4 a00 = p0[lane * 2], a01 = p0[lane * 2 + 1];
    float4 a10 = p1[lane * 2], a11 = p1[lane * 2 + 1];
    float bias0 = dec_bih[R0] + dec_bhh[R0];
    float bias1 = dec_bih[R1] + dec_bhh[R1];
#pragma unroll 1
    for (int tk = 0; tk < NV; tk++) {
        const float4* xv = (const float4*)(xs + tk * HID) + lane * 2;
        float4 x0 = xv[0], x1 = xv[1];
        float s0 = red32(dot8(a00, a01, x0, x1));
        float s1 = red32(dot8(a10, a11, x0, x1));
        if (lane == 0) {
            g_tab[tk * 1024 + u0 * 4 + g0] = s0 + bias0;
            g_tab[tk * 1024 + u1 * 4 + g1] = s1 + bias1;
        }
    }
    __syncthreads();
    if (tid == 0) st_rel_gpu(&g_flag[g], 1);
}

// ================= kernel 2: LSTM (enc table in-prologue, parallel DSMEM stores) =================
__global__ void __launch_bounds__(TPB, 1) __cluster_dims__(CS, 1, 1) vae_kernel(
    const int* data, const int* data_c, const int* target_c, const float* cond_emb,
    const float* enc_emb, const float* enc_Wih, const float* enc_Whh,
    const float* enc_bih, const float* enc_bhh,
    const float* hmu_W, const float* hmu_b, const float* cmu_W, const float* cmu_b,
    const float* fc1_W, const float* fc1_b, const float* fc2_W, const float* fc2_b,
    const float* dec_Whh,
    const float* out_W, const float* out_b,
    float* out, int out_size)
{
    extern __shared__ __align__(16) float sm[];
    float* h3b    = sm + O_H3B;
    float* cfull  = sm + O_CF;
    float* pre_sh = sm + O_PRE;
    float* tab_sh = sm + O_TAB;
    float* cat_h  = sm + O_CATH;
    float* cat_c  = sm + O_CATC;
    float* cnew_sh= sm + O_CNEW;
    float* xs_sh  = sm + O_XS;
    volatile ull* wmax_sh = (volatile ull*)(sm + O_WMAX);

    const int tid  = threadIdx.x;
    const int w    = tid >> 5;
    const int lane = tid & 31;
    const int b    = blockIdx.x;
    const int uu   = (lane >> 2) & 1;

    const uint32_t base   = smem_u32(sm);
    const uint32_t myrmap = mapa_u32(base, (uint32_t)(lane & 7));  // per-lane remote base

    // ---- stage enc inputs xs[t] = enc_emb[data[t]] ----
    for (int i = tid; i < ENCL * 64; i += TPB) {
        int t = i >> 6, c4 = i & 63;
        ((float4*)xs_sh)[i] = ((const float4*)(enc_emb + data[t] * HID))[c4];
    }

    // ---- enc input-projection table (per-CTA slice) using enc_Wih in regs ----
    ull wr[8][4];
    load_w8(enc_Wih, b, w, lane, wr);
    float ebias = 0.f;
    if (lane < 8) {
        int row = (lane & 3) * HID + b * 32 + 2 * w + (lane >> 2);
        ebias = enc_bih[row] + enc_bhh[row];
    }
    __syncthreads();                                  // xs ready
#pragma unroll 1
    for (int t = 0; t < ENCL; t++) {
        const ulonglong2* xv = (const ulonglong2*)(xs_sh + t * HID);
        ulonglong2 X = xv[lane * 2], Y = xv[lane * 2 + 1];
        float a[8];
#pragma unroll
        for (int r = 0; r < 8; r++) {
            ull ac = 0ull;
            ffma2(ac, wr[r][0], X.x); ffma2(ac, wr[r][1], X.y);
            ffma2(ac, wr[r][2], Y.x); ffma2(ac, wr[r][3], Y.y);
            a[r] = ups(ac);
        }
        float tot = reduce8(a[0], a[1], a[2], a[3], a[4], a[5], a[6], a[7], lane);
        if (lane < 8)
            pre_sh[t * 128 + (2 * w + (lane >> 2)) * 4 + (lane & 3)] = tot + ebias;
    }

    // ---- recurrent weights (encoder) ----
    load_w8(enc_Whh, b, w, lane, wr);

    // L2 prefetch serial-path weights
    for (int i = tid; i < 1024; i += TPB) {
        int gi = i >> 8, off = i & 255;
        pf_l2((const char*)(dec_Whh + (gi * 256 + b * 32) * HID) + off * 128);
    }
    for (int i = tid; i < 256; i += TPB) {
        pf_l2((const char*)hmu_W + i * 128);
        pf_l2((const char*)cmu_W + i * 128);
    }
    for (int i = tid; i < 320; i += TPB) {
        pf_l2((const char*)fc1_W + i * 128);
        pf_l2((const char*)fc2_W + i * 128);
    }
    for (int i = tid; i < 224; i += TPB)
        pf_l2((const char*)out_W + i * 128);

    // ---- h0 (slot 0) + c0 ----
    const int dcid = data_c[0], tcid = target_c[0];
    if (tid < HID) {
        float v = (tid >= HID - 8) ? cond_emb[dcid * 8 + (tid - (HID - 8))] : 0.f;
        h3b[tid] = v;
    }
    int ug = b * 32 + 2 * w + uu;
    float creg = (ug >= HID - 8) ? cond_emb[dcid * 8 + (ug - (HID - 8))] : 0.f;

    __syncthreads();
    cluster_bar();

    // ================= encoder: n = 0..15 =================
#pragma unroll 1
    for (int n = 0; n < ENCL; n++) {
        int slot = n % 3, slot2 = (n + 1) % 3;
        const ulonglong2* hp = (const ulonglong2*)(h3b + slot * HID);
        ulonglong2 X = hp[lane * 2], Y = hp[lane * 2 + 1];
        float a[8];
#pragma unroll
        for (int r = 0; r < 8; r++) {
            ull ac = 0ull;
            ffma2(ac, wr[r][0], X.x); ffma2(ac, wr[r][1], X.y);
            ffma2(ac, wr[r][2], Y.x); ffma2(ac, wr[r][3], Y.y);
            a[r] = ups(ac);
        }
        float tot = reduce8(a[0], a[1], a[2], a[3], a[4], a[5], a[6], a[7], lane);
        int gb = lane & 28;
        float g0 = __shfl_sync(FULLM, tot, gb);
        float g1 = __shfl_sync(FULLM, tot, gb | 1);
        float g2 = __shfl_sync(FULLM, tot, gb | 2);
        float g3 = __shfl_sync(FULLM, tot, gb | 3);
        float4 pr = *(const float4*)(pre_sh + n * 128 + (2 * w + uu) * 4);
        float gi = g0 + pr.x, gf = g1 + pr.y, gg = g2 + pr.z, go = g3 + pr.w;
        float c = sigf(gf) * creg + sigf(gi) * tanhfast(gg);
        float h = sigf(go) * tanhfast(c);
        creg = c;
        float hA = __shfl_sync(FULLM, h, 0);
        float hB = __shfl_sync(FULLM, h, 4);
        if (lane < 8) {                               // 8 ranks in ONE warp instruction
            ull hp2 = pack2(hA, hB);
            uint32_t off = (uint32_t)((slot2 * HID + b * 32 + 2 * w) * 4);
            st_cluster_b64(myrmap + off, hp2);
        }
        if (n == ENCL - 1) {
            float cA = __shfl_sync(FULLM, c, 0);
            float cB = __shfl_sync(FULLM, c, 4);
            if (lane < 8) {
                ull cp = pack2(cA, cB);
                uint32_t co = (uint32_t)((O_CF + b * 32 + 2 * w) * 4);
                st_cluster_b64(myrmap + co, cp);
            }
        }
        cluster_bar();
    }

    // ================= latent heads + decoder init (redundant per CTA) =================
    {
        const float4* hv = (const float4*)(h3b + HID) + lane * 2;
        float4 h0v = hv[0], h1v = hv[1];
        const float4* cv = (const float4*)cfull + lane * 2;
        float4 c0v = cv[0], c1v = cv[1];
#pragma unroll
        for (int half = 0; half < 2; half++) {
            int rr = w + half * 16;
            const float4* pp = (const float4*)(hmu_W + rr * HID);
            float4 x0 = pp[lane * 2], x1 = pp[lane * 2 + 1];
            float s = red32(dot8(x0, x1, h0v, h1v));
            if (lane == 0) cat_h[rr] = s + hmu_b[rr];
            pp = (const float4*)(cmu_W + rr * HID);
            x0 = pp[lane * 2]; x1 = pp[lane * 2 + 1];
            s = red32(dot8(x0, x1, c0v, c1v));
            if (lane == 0) cat_c[rr] = s + cmu_b[rr];
        }
    }
    if (tid < 8) {
        float v = cond_emb[tcid * 8 + tid];
        cat_h[32 + tid] = v; cat_c[32 + tid] = v;
    }
    __syncthreads();
    float newv = 0.f;
    if (tid < HID) {
        float s = fc1_b[tid];
        const float* wrp = fc1_W + tid * 40;
#pragma unroll
        for (int k = 0; k < 40; k++) s += cat_h[k] * wrp[k];
        newv = s;
    }
    if (tid < 32) {
        int j = b * 32 + tid;
        float s = fc2_b[j];
        const float* wrp = fc2_W + j * 40;
#pragma unroll
        for (int k = 0; k < 40; k++) s += cat_c[k] * wrp[k];
        cnew_sh[tid] = s;
    }
    __syncthreads();
    if (tid < HID) h3b[2 * HID + tid] = newv;           // dh -> slot 2 (= h(17))
    creg = cnew_sh[2 * w + uu];

    // decoder token table (forked kernel finished ~25 us ago; wait is instant)
    if (tid < 64) while (ld_acq_gpu(&g_flag[tid]) == 0) { }
    __syncthreads();
    for (int i = tid; i < NV * 32; i += TPB)
        ((float4*)tab_sh)[i] = ((const float4*)g_tab)[(i >> 5) * 256 + b * 32 + (i & 31)];

    // decoder weights + out_W rows (2 per warp, w<14) into registers
    load_w8(dec_Whh, b, w, lane, wr);
    ull owr[2][4];
    {
        int lw = (w < 14) ? w : 0;
#pragma unroll
        for (int rr = 0; rr < 2; rr++) {
            const ulonglong2* p = (const ulonglong2*)(out_W + (2 * lw + rr) * HID + 8 * lane);
            ulonglong2 v0 = p[0], v1 = p[1];
            owr[rr][0] = v0.x; owr[rr][1] = v0.y; owr[rr][2] = v1.x; owr[rr][3] = v1.y;
        }
    }
    float obv = (w < 14) ? out_b[2 * w + (lane & 1)] : 0.f;
    __syncthreads();

    // ================= decoder: N = 17..41 =================
#pragma unroll 1
    for (int N = 17; N < 17 + DECL; N++) {
        int slot = N % 3, slot2 = (N + 1) % 3, ph = N & 1;
        const ulonglong2* hp = (const ulonglong2*)(h3b + slot * HID);
        ulonglong2 X = hp[lane * 2], Y = hp[lane * 2 + 1];

        float lgv = 0.f;
        if (w < 14 && N > 17) {
            ull la0 = 0ull, la1 = 0ull;
            ffma2(la0, owr[0][0], X.x); ffma2(la0, owr[0][1], X.y);
            ffma2(la0, owr[0][2], Y.x); ffma2(la0, owr[0][3], Y.y);
            ffma2(la1, owr[1][0], X.x); ffma2(la1, owr[1][1], X.y);
            ffma2(la1, owr[1][2], Y.x); ffma2(la1, owr[1][3], Y.y);
            lgv = reduce2(ups(la0), ups(la1), lane) + obv;
            uint32_t bits = __float_as_uint(lgv);
            uint32_t key = (bits & 0x80000000u) ? ~bits : (bits | 0x80000000u);
            int row = 2 * w + (lane & 1);
            ull cmp = ((ull)key << 8) | (ull)(255 - row);
            ull c1 = __shfl_xor_sync(FULLM, cmp, 1);
            if (c1 > cmp) cmp = c1;
            if (lane == 0) wmax_sh[ph * 16 + w] = cmp;
        }

        float a[8];
#pragma unroll
        for (int r = 0; r < 8; r++) {
            ull ac = 0ull;
            ffma2(ac, wr[r][0], X.x); ffma2(ac, wr[r][1], X.y);
            ffma2(ac, wr[r][2], Y.x); ffma2(ac, wr[r][3], Y.y);
            a[r] = ups(ac);
        }
        float tot = reduce8(a[0], a[1], a[2], a[3], a[4], a[5], a[6], a[7], lane);

        __syncthreads();

        int tok = 0;
        if (N > 17) {
            ull v = (lane < 14) ? wmax_sh[ph * 16 + lane] : 0ull;
#pragma unroll
            for (int o = 1; o < 32; o <<= 1) {
                ull ot = __shfl_xor_sync(FULLM, v, o);
                if (ot > v) v = ot;
            }
            tok = 255 - (int)(v & 0xffu);
            if (b == 0) {
                if (w < 14 && lane < 2) out[(N - 18) * NV + 2 * w + lane] = lgv;
                if (w == 15 && lane == 0) out[NV * DECL + (N - 18)] = (float)tok;
            }
        }

        int gb = lane & 28;
        float g0 = __shfl_sync(FULLM, tot, gb);
        float g1 = __shfl_sync(FULLM, tot, gb | 1);
        float g2 = __shfl_sync(FULLM, tot, gb | 2);
        float g3 = __shfl_sync(FULLM, tot, gb | 3);
        float4 pr = *(const float4*)(tab_sh + tok * 128 + (2 * w + uu) * 4);
        float gi = g0 + pr.x, gf = g1 + pr.y, gg = g2 + pr.z, go = g3 + pr.w;
        float c = sigf(gf) * creg + sigf(gi) * tanhfast(gg);
        float h = sigf(go) * tanhfast(c);
        creg = c;
        float hA = __shfl_sync(FULLM, h, 0);
        float hB = __shfl_sync(FULLM, h, 4);
        if (lane < 8) {
            ull hp2 = pack2(hA, hB);
            uint32_t off = (uint32_t)((slot2 * HID + b * 32 + 2 * w) * 4);
            st_cluster_b64(myrmap + off, hp2);
        }
        cluster_bar();
    }

    // ---- tail: logits/argmax of h(42) (slot 0) ----
    if (b == 0) {
        const ulonglong2* hp = (const ulonglong2*)h3b;
        ulonglong2 X = hp[lane * 2], Y = hp[lane * 2 + 1];
        float lgv = 0.f;
        if (w < 14) {
            ull la0 = 0ull, la1 = 0ull;
            ffma2(la0, owr[0][0], X.x); ffma2(la0, owr[0][1], X.y);
            ffma2(la0, owr[0][2], Y.x); ffma2(la0, owr[0][3], Y.y);
            ffma2(la1, owr[1][0], X.x); ffma2(la1, owr[1][1], X.y);
            ffma2(la1, owr[1][2], Y.x); ffma2(la1, owr[1][3], Y.y);
            lgv = reduce2(ups(la0), ups(la1), lane) + obv;
            uint32_t bits = __float_as_uint(lgv);
            uint32_t key = (bits & 0x80000000u) ? ~bits : (bits | 0x80000000u);
            int row = 2 * w + (lane & 1);
            ull cmp = ((ull)key << 8) | (ull)(255 - row);
            ull c1 = __shfl_xor_sync(FULLM, cmp, 1);
            if (c1 > cmp) cmp = c1;
            if (lane == 0) wmax_sh[w] = cmp;
            if (lane < 2) out[(DECL - 1) * NV + row] = lgv;
        }
        __syncthreads();
        if (w == 15) {
            ull v = (lane < 14) ? wmax_sh[lane] : 0ull;
#pragma unroll
            for (int o = 1; o < 32; o <<= 1) {
                ull ot = __shfl_xor_sync(FULLM, v, o);
                if (ot > v) v = ot;
            }
            if (lane == 0)
                out[NV * DECL + (DECL - 1)] = (float)(255 - (int)(v & 0xffu));
        }
        // reset flags for the next graph replay (replays serialize, so safe)
        if (tid < 64) g_flag[tid] = 0;
    }
    cluster_bar();
    (void)out_size; (void)ug;
}

// host-side fork/join resources (created once, on the uncaptured correctness call)
struct HxCtx {
    cudaStream_t s2;
    cudaEvent_t  eF, eJ;
    HxCtx() {
        cudaStreamCreateWithFlags(&s2, cudaStreamNonBlocking);
        cudaEventCreateWithFlags(&eF, cudaEventDisableTiming);
        cudaEventCreateWithFlags(&eJ, cudaEventDisableTiming);
    }
};
static HxCtx& hx_ctx() { static HxCtx c; return c; }

extern "C" void kernel_launch(void* const* d_in, const int* in_sizes, int n_in,
                              void* d_out, int out_size) {
    (void)in_sizes; (void)n_in;
    const int*   data     = (const int*)  d_in[0];
    const int*   data_c   = (const int*)  d_in[1];
    const int*   target_c = (const int*)  d_in[2];
    const float* cond_emb = (const float*)d_in[3];
    const float* enc_emb  = (const float*)d_in[4];
    const float* enc_Wih  = (const float*)d_in[5];
    const float* enc_Whh  = (const float*)d_in[6];
    const float* enc_bih  = (const float*)d_in[7];
    const float* enc_bhh  = (const float*)d_in[8];
    const float* hmu_W    = (const float*)d_in[9];
    const float* hmu_b    = (const float*)d_in[10];
    const float* cmu_W    = (const float*)d_in[11];
    const float* cmu_b    = (const float*)d_in[12];
    const float* fc1_W    = (const float*)d_in[13];
    const float* fc1_b    = (const float*)d_in[14];
    const float* fc2_W    = (const float*)d_in[15];
    const float* fc2_b    = (const float*)d_in[16];
    const float* dec_emb  = (const float*)d_in[17];
    const float* dec_Wih  = (const float*)d_in[18];
    const float* dec_Whh  = (const float*)d_in[19];
    const float* dec_bih  = (const float*)d_in[20];
    const float* dec_bhh  = (const float*)d_in[21];
    const float* out_W    = (const float*)d_in[22];
    const float* out_b    = (const float*)d_in[23];

    HxCtx& c = hx_ctx();

    // fork: dec-table kernel runs fully overlapped with the LSTM kernel
    cudaEventRecord(c.eF, 0);
    cudaStreamWaitEvent(c.s2, c.eF, 0);
    dec_table_kernel<<<64, 256, 0, c.s2>>>(dec_Wih, dec_bih, dec_bhh, dec_emb);
    cudaEventRecord(c.eJ, c.s2);

    cudaFuncSetAttribute(vae_kernel, cudaFuncAttributeMaxDynamicSharedMemorySize, SMEM_BYTES);
    vae_kernel<<<CS, TPB, SMEM_BYTES>>>(data, data_c, target_c, cond_emb,
                                        enc_emb, enc_Wih, enc_Whh, enc_bih, enc_bhh,
                                        hmu_W, hmu_b, cmu_W, cmu_b,
                                        fc1_W, fc1_b, fc2_W, fc2_b,
                                        dec_Whh,
                                        out_W, out_b,
                                        (float*)d_out, out_size);
    cudaStreamWaitEvent(0, c.eJ, 0);
}

// round 12
// speedup vs baseline: 1.5899x; 1.0537x over previous
#include <cuda_runtime.h>
#include <math.h>
#include <stdint.h>

#define CS   8
#define TPB  512
#define HID  256
#define ENCL 16
#define DECL 25
#define NV   28

typedef unsigned long long ull;
#define FULLM 0xffffffffu

// projection tables, layout [t][unit 0..255][gate 0..3]
__device__ float g_pre[ENCL * 1024];
__device__ float g_tab[NV * 1024];
__device__ int   g_flag[64];         // [0..31] enc CTA done, [32..63] dec CTA done

// ---------------- smem layout (float offsets) ----------------
#define O_H3B   0               // 3 x 256 h ring
#define O_CF    768             // cfull [256]
#define O_PRE   1024            // [16][32 units][4 gates] = 2048
#define O_TAB   3072            // [28][32][4] = 3584
#define O_CATH  6656            // [40]
#define O_CATC  6696            // [40]
#define O_CNEW  6736            // [32]
#define O_WMAX  6768            // 2 phases x 16 ull = 64 floats
#define SMEM_FLOATS 6832
#define SMEM_BYTES  (SMEM_FLOATS * 4)

// ---------------- PTX helpers ----------------
__device__ __forceinline__ uint32_t smem_u32(const void* p) {
    uint32_t a;
    asm("{ .reg .u64 t; cvta.to.shared.u64 t, %1; cvt.u32.u64 %0, t; }" : "=r"(a) : "l"(p));
    return a;
}
__device__ __forceinline__ uint32_t mapa_u32(uint32_t a, uint32_t rank) {
    uint32_t r;
    asm("mapa.shared::cluster.u32 %0, %1, %2;" : "=r"(r) : "r"(a), "r"(rank));
    return r;
}
__device__ __forceinline__ void st_cluster_b64(uint32_t addr, ull v) {
    asm volatile("st.shared::cluster.b64 [%0], %1;" :: "r"(addr), "l"(v) : "memory");
}
__device__ __forceinline__ void cluster_bar() {
    asm volatile("barrier.cluster.arrive.aligned;" ::: "memory");
    asm volatile("barrier.cluster.wait.aligned;" ::: "memory");
}
__device__ __forceinline__ int ld_acq_gpu(const int* p) {
    int v;
    asm volatile("ld.acquire.gpu.global.s32 %0, [%1];" : "=r"(v) : "l"(p) : "memory");
    return v;
}
__device__ __forceinline__ void st_rel_gpu(int* p, int v) {
    asm volatile("st.release.gpu.global.s32 [%0], %1;" :: "l"(p), "r"(v) : "memory");
}
__device__ __forceinline__ void ffma2(ull &acc, ull a, ull b) {
    asm("fma.rn.f32x2 %0, %1, %2, %0;" : "+l"(acc) : "l"(a), "l"(b));
}
__device__ __forceinline__ float ups(ull a) {
    float lo, hi;
    asm("mov.b64 {%0,%1}, %2;" : "=f"(lo), "=f"(hi) : "l"(a));
    return lo + hi;
}
__device__ __forceinline__ ull pack2(float lo, float hi) {
    ull r;
    asm("mov.b64 %0, {%1,%2};" : "=l"(r) : "f"(lo), "f"(hi));
    return r;
}
__device__ __forceinline__ float sigf(float x) { return __fdividef(1.f, 1.f + __expf(-x)); }
__device__ __forceinline__ float tanhfast(float x) {
    float t = __expf(-2.f * fabsf(x));
    return copysignf(__fdividef(1.f - t, 1.f + t), x);
}
__device__ __forceinline__ float red32(float s) {
#pragma unroll
    for (int o = 16; o > 0; o >>= 1) s += __shfl_xor_sync(FULLM, s, o);
    return s;
}
__device__ __forceinline__ float dot8(float4 a0, float4 a1, float4 b0, float4 b1) {
    return a0.x*b0.x + a0.y*b0.y + a0.z*b0.z + a0.w*b0.w
         + a1.x*b1.x + a1.y*b1.y + a1.z*b1.z + a1.w*b1.w;
}
__device__ __forceinline__ void pf_l2(const void* p) {
    asm volatile("prefetch.global.L2 [%0];" :: "l"(p));
}

// 8 gate-row weight chunks (lane's 8 h-elems) for this warp
__device__ __forceinline__ void load_w8(const float* W, int b, int w, int lane, ull wr[8][4]) {
#pragma unroll
    for (int r = 0; r < 8; r++) {
        int row = (r & 3) * HID + b * 32 + 2 * w + (r >> 2);
        const ulonglong2* p = (const ulonglong2*)(W + row * HID + 8 * lane);
        ulonglong2 v0 = p[0], v1 = p[1];
        wr[r][0] = v0.x; wr[r][1] = v0.y; wr[r][2] = v1.x; wr[r][3] = v1.y;
    }
}

// multi-acc butterfly: 8 partials/lane -> every lane holds total of acc (lane&7)
__device__ __forceinline__ float reduce8(float a0, float a1, float a2, float a3,
                                         float a4, float a5, float a6, float a7, int lane) {
    a0 += __shfl_xor_sync(FULLM, a0, 16); a1 += __shfl_xor_sync(FULLM, a1, 16);
    a2 += __shfl_xor_sync(FULLM, a2, 16); a3 += __shfl_xor_sync(FULLM, a3, 16);
    a4 += __shfl_xor_sync(FULLM, a4, 16); a5 += __shfl_xor_sync(FULLM, a5, 16);
    a6 += __shfl_xor_sync(FULLM, a6, 16); a7 += __shfl_xor_sync(FULLM, a7, 16);
    a0 += __shfl_xor_sync(FULLM, a0, 8);  a1 += __shfl_xor_sync(FULLM, a1, 8);
    a2 += __shfl_xor_sync(FULLM, a2, 8);  a3 += __shfl_xor_sync(FULLM, a3, 8);
    a4 += __shfl_xor_sync(FULLM, a4, 8);  a5 += __shfl_xor_sync(FULLM, a5, 8);
    a6 += __shfl_xor_sync(FULLM, a6, 8);  a7 += __shfl_xor_sync(FULLM, a7, 8);
    bool b2 = (lane >> 2) & 1;
    float s0 = b2 ? a0 : a4, s1 = b2 ? a1 : a5, s2 = b2 ? a2 : a6, s3 = b2 ? a3 : a7;
    float r0 = __shfl_xor_sync(FULLM, s0, 4), r1 = __shfl_xor_sync(FULLM, s1, 4);
    float r2 = __shfl_xor_sync(FULLM, s2, 4), r3 = __shfl_xor_sync(FULLM, s3, 4);
    float k0 = (b2 ? a4 : a0) + r0, k1 = (b2 ? a5 : a1) + r1;
    float k2 = (b2 ? a6 : a2) + r2, k3 = (b2 ? a7 : a3) + r3;
    bool b1 = (lane >> 1) & 1;
    float t0 = b1 ? k0 : k2, t1 = b1 ? k1 : k3;
    float u0 = __shfl_xor_sync(FULLM, t0, 2), u1 = __shfl_xor_sync(FULLM, t1, 2);
    float m0 = (b1 ? k2 : k0) + u0, m1 = (b1 ? k3 : k1) + u1;
    bool b0 = lane & 1;
    float sv = b0 ? m0 : m1;
    float rv = __shfl_xor_sync(FULLM, sv, 1);
    return (b0 ? m1 : m0) + rv;
}
// 2-acc reduce: every lane gets total of acc (lane&1)
__device__ __forceinline__ float reduce2(float l0, float l1, int lane) {
    l0 += __shfl_xor_sync(FULLM, l0, 16); l1 += __shfl_xor_sync(FULLM, l1, 16);
    l0 += __shfl_xor_sync(FULLM, l0, 8);  l1 += __shfl_xor_sync(FULLM, l1, 8);
    l0 += __shfl_xor_sync(FULLM, l0, 4);  l1 += __shfl_xor_sync(FULLM, l1, 4);
    l0 += __shfl_xor_sync(FULLM, l0, 2);  l1 += __shfl_xor_sync(FULLM, l1, 2);
    bool b0 = lane & 1;
    float s = b0 ? l0 : l1;
    float r = __shfl_xor_sync(FULLM, s, 1);
    return (b0 ? l1 : l0) + r;
}

// ================= kernel 1: tables (64 CTAs; enc/dec halves run in PARALLEL) =================
__global__ void __launch_bounds__(256) table_kernel(
    const int* data,
    const float* enc_Wih, const float* enc_bih, const float* enc_bhh, const float* enc_emb,
    const float* dec_Wih, const float* dec_bih, const float* dec_bhh, const float* dec_emb)
{
    __shared__ __align__(16) float xs[NV * HID];     // staging (enc uses 16 rows, dec 28)
    const int tid  = threadIdx.x;
    const int w    = tid >> 5;
    const int lane = tid & 31;
    const int g    = blockIdx.x;

    if (g < 32) {
        // ---- enc: rows g*32 + w*4 + (0..3), over 16 timesteps ----
        for (int i = tid; i < ENCL * 64; i += 256) {
            int t = i >> 6, c4 = i & 63;
            ((float4*)xs)[i] = ((const float4*)(enc_emb + data[t] * HID))[c4];
        }
        __syncthreads();
        int Rb = g * 32 + w * 4;
        float4 aw[4][2]; float bias[4];
#pragma unroll
        for (int r = 0; r < 4; r++) {
            const float4* p = (const float4*)(enc_Wih + (Rb + r) * HID);
            aw[r][0] = p[lane * 2]; aw[r][1] = p[lane * 2 + 1];
            bias[r] = enc_bih[Rb + r] + enc_bhh[Rb + r];
        }
#pragma unroll 1
        for (int t = 0; t < ENCL; t++) {
            const float4* xv = (const float4*)(xs + t * HID) + lane * 2;
            float4 x0 = xv[0], x1 = xv[1];
#pragma unroll
            for (int r = 0; r < 4; r++) {
                float s = red32(dot8(aw[r][0], aw[r][1], x0, x1));
                if (lane == 0) {
                    int R = Rb + r;
                    g_pre[t * 1024 + (R & 255) * 4 + (R >> 8)] = s + bias[r];
                }
            }
        }
        __syncthreads();
        if (tid == 0) st_rel_gpu(&g_flag[g], 1);
    } else {
        // ---- dec: rows (g-32)*32 + w*4 + (0..3), over 28 tokens ----
        for (int i = tid; i < NV * 64; i += 256) {
            int tk = i >> 6, c4 = i & 63;
            float4 v = ((const float4*)(dec_emb + tk * HID))[c4];
            v.x = fmaxf(v.x, 0.f); v.y = fmaxf(v.y, 0.f);
            v.z = fmaxf(v.z, 0.f); v.w = fmaxf(v.w, 0.f);
            ((float4*)xs)[i] = v;
        }
        __syncthreads();
        int Rb = (g - 32) * 32 + w * 4;
        float4 aw[4][2]; float bias[4];
#pragma unroll
        for (int r = 0; r < 4; r++) {
            const float4* p = (const float4*)(dec_Wih + (Rb + r) * HID);
            aw[r][0] = p[lane * 2]; aw[r][1] = p[lane * 2 + 1];
            bias[r] = dec_bih[Rb + r] + dec_bhh[Rb + r];
        }
#pragma unroll 1
        for (int tk = 0; tk < NV; tk++) {
            const float4* xv = (const float4*)(xs + tk * HID) + lane * 2;
            float4 x0 = xv[0], x1 = xv[1];
#pragma unroll
            for (int r = 0; r < 4; r++) {
                float s = red32(dot8(aw[r][0], aw[r][1], x0, x1));
                if (lane == 0) {
                    int R = Rb + r;
                    g_tab[tk * 1024 + (R & 255) * 4 + (R >> 8)] = s + bias[r];
                }
            }
        }
        __syncthreads();
        if (tid == 0) st_rel_gpu(&g_flag[g], 1);
    }
}

// ================= kernel 2: lean-crossbar LSTM (R9 body, flag waits, per-lane stores) =================
__global__ void __launch_bounds__(TPB, 1) __cluster_dims__(CS, 1, 1) vae_kernel(
    const int* data_c, const int* target_c, const float* cond_emb,
    const float* enc_Whh,
    const float* hmu_W, const float* hmu_b, const float* cmu_W, const float* cmu_b,
    const float* fc1_W, const float* fc1_b, const float* fc2_W, const float* fc2_b,
    const float* dec_Whh,
    const float* out_W, const float* out_b,
    float* out, int out_size)
{
    extern __shared__ __align__(16) float sm[];
    float* h3b    = sm + O_H3B;
    float* cfull  = sm + O_CF;
    float* pre_sh = sm + O_PRE;
    float* tab_sh = sm + O_TAB;
    float* cat_h  = sm + O_CATH;
    float* cat_c  = sm + O_CATC;
    float* cnew_sh= sm + O_CNEW;
    volatile ull* wmax_sh = (volatile ull*)(sm + O_WMAX);

    const int tid  = threadIdx.x;
    const int w    = tid >> 5;
    const int lane = tid & 31;
    const int b    = blockIdx.x;
    const int uu   = (lane >> 2) & 1;

    const uint32_t base   = smem_u32(sm);
    const uint32_t myrmap = mapa_u32(base, (uint32_t)(lane & 7));

    // encoder recurrent weights (cold DRAM ~ overlaps table kernel's enc work)
    ull wr[8][4];
    load_w8(enc_Whh, b, w, lane, wr);

    // L2 prefetch serial-path weights
    for (int i = tid; i < 1024; i += TPB) {
        int gi = i >> 8, off = i & 255;
        pf_l2((const char*)(dec_Whh + (gi * 256 + b * 32) * HID) + off * 128);
    }
    for (int i = tid; i < 256; i += TPB) {
        pf_l2((const char*)hmu_W + i * 128);
        pf_l2((const char*)cmu_W + i * 128);
    }
    for (int i = tid; i < 320; i += TPB) {
        pf_l2((const char*)fc1_W + i * 128);
        pf_l2((const char*)fc2_W + i * 128);
    }
    for (int i = tid; i < 224; i += TPB)
        pf_l2((const char*)out_W + i * 128);

    // ---- h0 (slot 0) + c0 ----
    const int dcid = data_c[0], tcid = target_c[0];
    if (tid < HID) {
        float v = (tid >= HID - 8) ? cond_emb[dcid * 8 + (tid - (HID - 8))] : 0.f;
        h3b[tid] = v;
    }
    int ug = b * 32 + 2 * w + uu;
    float creg = (ug >= HID - 8) ? cond_emb[dcid * 8 + (ug - (HID - 8))] : 0.f;

    // wait for enc table (parallel fork; short wait), copy slice
    if (tid < 32) while (ld_acq_gpu(&g_flag[tid]) == 0) { }
    __syncthreads();
    for (int i = tid; i < ENCL * 32; i += TPB)
        ((float4*)pre_sh)[i] = ((const float4*)g_pre)[(i >> 5) * 256 + b * 32 + (i & 31)];

    __syncthreads();
    cluster_bar();

    // ================= encoder: n = 0..15 =================
#pragma unroll 1
    for (int n = 0; n < ENCL; n++) {
        int slot = n % 3, slot2 = (n + 1) % 3;
        const ulonglong2* hp = (const ulonglong2*)(h3b + slot * HID);
        ulonglong2 X = hp[lane * 2], Y = hp[lane * 2 + 1];
        float a[8];
#pragma unroll
        for (int r = 0; r < 8; r++) {
            ull ac = 0ull;
            ffma2(ac, wr[r][0], X.x); ffma2(ac, wr[r][1], X.y);
            ffma2(ac, wr[r][2], Y.x); ffma2(ac, wr[r][3], Y.y);
            a[r] = ups(ac);
        }
        float tot = reduce8(a[0], a[1], a[2], a[3], a[4], a[5], a[6], a[7], lane);
        int gb = lane & 28;
        float g0 = __shfl_sync(FULLM, tot, gb);
        float g1 = __shfl_sync(FULLM, tot, gb | 1);
        float g2 = __shfl_sync(FULLM, tot, gb | 2);
        float g3 = __shfl_sync(FULLM, tot, gb | 3);
        float4 pr = *(const float4*)(pre_sh + n * 128 + (2 * w + uu) * 4);
        float gi = g0 + pr.x, gf = g1 + pr.y, gg = g2 + pr.z, go = g3 + pr.w;
        float c = sigf(gf) * creg + sigf(gi) * tanhfast(gg);
        float h = sigf(go) * tanhfast(c);
        creg = c;
        float hA = __shfl_sync(FULLM, h, 0);
        float hB = __shfl_sync(FULLM, h, 4);
        if (lane < 8) {                               // 8 ranks in ONE warp instruction
            ull hp2 = pack2(hA, hB);
            uint32_t off = (uint32_t)((slot2 * HID + b * 32 + 2 * w) * 4);
            st_cluster_b64(myrmap + off, hp2);
        }
        if (n == ENCL - 1) {
            float cA = __shfl_sync(FULLM, c, 0);
            float cB = __shfl_sync(FULLM, c, 4);
            if (lane < 8) {
                ull cp = pack2(cA, cB);
                uint32_t co = (uint32_t)((O_CF + b * 32 + 2 * w) * 4);
                st_cluster_b64(myrmap + co, cp);
            }
        }
        cluster_bar();
    }

    // ================= latent heads + decoder init (redundant per CTA) =================
    {
        const float4* hv = (const float4*)(h3b + HID) + lane * 2;
        float4 h0v = hv[0], h1v = hv[1];
        const float4* cv = (const float4*)cfull + lane * 2;
        float4 c0v = cv[0], c1v = cv[1];
#pragma unroll
        for (int half = 0; half < 2; half++) {
            int rr = w + half * 16;
            const float4* pp = (const float4*)(hmu_W + rr * HID);
            float4 x0 = pp[lane * 2], x1 = pp[lane * 2 + 1];
            float s = red32(dot8(x0, x1, h0v, h1v));
            if (lane == 0) cat_h[rr] = s + hmu_b[rr];
            pp = (const float4*)(cmu_W + rr * HID);
            x0 = pp[lane * 2]; x1 = pp[lane * 2 + 1];
            s = red32(dot8(x0, x1, c0v, c1v));
            if (lane == 0) cat_c[rr] = s + cmu_b[rr];
        }
    }
    if (tid < 8) {
        float v = cond_emb[tcid * 8 + tid];
        cat_h[32 + tid] = v; cat_c[32 + tid] = v;
    }
    __syncthreads();
    float newv = 0.f;
    if (tid < HID) {
        float s = fc1_b[tid];
        const float* wrp = fc1_W + tid * 40;
#pragma unroll
        for (int k = 0; k < 40; k++) s += cat_h[k] * wrp[k];
        newv = s;
    }
    if (tid < 32) {
        int j = b * 32 + tid;
        float s = fc2_b[j];
        const float* wrp = fc2_W + j * 40;
#pragma unroll
        for (int k = 0; k < 40; k++) s += cat_c[k] * wrp[k];
        cnew_sh[tid] = s;
    }
    __syncthreads();
    if (tid < HID) h3b[2 * HID + tid] = newv;           // dh -> slot 2 (= h(17))
    creg = cnew_sh[2 * w + uu];

    // decoder token table (long since built); copy slice
    if (tid < 32) while (ld_acq_gpu(&g_flag[32 + tid]) == 0) { }
    __syncthreads();
    for (int i = tid; i < NV * 32; i += TPB)
        ((float4*)tab_sh)[i] = ((const float4*)g_tab)[(i >> 5) * 256 + b * 32 + (i & 31)];

    // decoder weights + out_W rows (2 per warp, w<14) into registers
    load_w8(dec_Whh, b, w, lane, wr);
    ull owr[2][4];
    {
        int lw = (w < 14) ? w : 0;
#pragma unroll
        for (int rr = 0; rr < 2; rr++) {
            const ulonglong2* p = (const ulonglong2*)(out_W + (2 * lw + rr) * HID + 8 * lane);
            ulonglong2 v0 = p[0], v1 = p[1];
            owr[rr][0] = v0.x; owr[rr][1] = v0.y; owr[rr][2] = v1.x; owr[rr][3] = v1.y;
        }
    }
    float obv = (w < 14) ? out_b[2 * w + (lane & 1)] : 0.f;
    __syncthreads();

    // ================= decoder: N = 17..41 =================
#pragma unroll 1
    for (int N = 17; N < 17 + DECL; N++) {
        int slot = N % 3, slot2 = (N + 1) % 3, ph = N & 1;
        const ulonglong2* hp = (const ulonglong2*)(h3b + slot * HID);
        ulonglong2 X = hp[lane * 2], Y = hp[lane * 2 + 1];

        float lgv = 0.f;
        if (w < 14 && N > 17) {
            ull la0 = 0ull, la1 = 0ull;
            ffma2(la0, owr[0][0], X.x); ffma2(la0, owr[0][1], X.y);
            ffma2(la0, owr[0][2], Y.x); ffma2(la0, owr[0][3], Y.y);
            ffma2(la1, owr[1][0], X.x); ffma2(la1, owr[1][1], X.y);
            ffma2(la1, owr[1][2], Y.x); ffma2(la1, owr[1][3], Y.y);
            lgv = reduce2(ups(la0), ups(la1), lane) + obv;
            uint32_t bits = __float_as_uint(lgv);
            uint32_t key = (bits & 0x80000000u) ? ~bits : (bits | 0x80000000u);
            int row = 2 * w + (lane & 1);
            ull cmp = ((ull)key << 8) | (ull)(255 - row);
            ull c1 = __shfl_xor_sync(FULLM, cmp, 1);
            if (c1 > cmp) cmp = c1;
            if (lane == 0) wmax_sh[ph * 16 + w] = cmp;
        }

        float a[8];
#pragma unroll
        for (int r = 0; r < 8; r++) {
            ull ac = 0ull;
            ffma2(ac, wr[r][0], X.x); ffma2(ac, wr[r][1], X.y);
            ffma2(ac, wr[r][2], Y.x); ffma2(ac, wr[r][3], Y.y);
            a[r] = ups(ac);
        }
        float tot = reduce8(a[0], a[1], a[2], a[3], a[4], a[5], a[6], a[7], lane);

        __syncthreads();

        int tok = 0;
        if (N > 17) {
            ull v = (lane < 14) ? wmax_sh[ph * 16 + lane] : 0ull;
#pragma unroll
            for (int o = 1; o < 32; o <<= 1) {
                ull ot = __shfl_xor_sync(FULLM, v, o);
                if (ot > v) v = ot;
            }
            tok = 255 - (int)(v & 0xffu);
            if (b == 0) {
                if (w < 14 && lane < 2) out[(N - 18) * NV + 2 * w + lane] = lgv;
                if (w == 15 && lane == 0) out[NV * DECL + (N - 18)] = (float)tok;
            }
        }

        int gb = lane & 28;
        float g0 = __shfl_sync(FULLM, tot, gb);
        float g1 = __shfl_sync(FULLM, tot, gb | 1);
        float g2 = __shfl_sync(FULLM, tot, gb | 2);
        float g3 = __shfl_sync(FULLM, tot, gb | 3);
        float4 pr = *(const float4*)(tab_sh + tok * 128 + (2 * w + uu) * 4);
        float gi = g0 + pr.x, gf = g1 + pr.y, gg = g2 + pr.z, go = g3 + pr.w;
        float c = sigf(gf) * creg + sigf(gi) * tanhfast(gg);
        float h = sigf(go) * tanhfast(c);
        creg = c;
        float hA = __shfl_sync(FULLM, h, 0);
        float hB = __shfl_sync(FULLM, h, 4);
        if (lane < 8) {
            ull hp2 = pack2(hA, hB);
            uint32_t off = (uint32_t)((slot2 * HID + b * 32 + 2 * w) * 4);
            st_cluster_b64(myrmap + off, hp2);
        }
        cluster_bar();
    }

    // ---- tail: logits/argmax of h(42) (slot 0) ----
    if (b == 0) {
        const ulonglong2* hp = (const ulonglong2*)h3b;
        ulonglong2 X = hp[lane * 2], Y = hp[lane * 2 + 1];
        float lgv = 0.f;
        if (w < 14) {
            ull la0 = 0ull, la1 = 0ull;
            ffma2(la0, owr[0][0], X.x); ffma2(la0, owr[0][1], X.y);
            ffma2(la0, owr[0][2], Y.x); ffma2(la0, owr[0][3], Y.y);
            ffma2(la1, owr[1][0], X.x); ffma2(la1, owr[1][1], X.y);
            ffma2(la1, owr[1][2], Y.x); ffma2(la1, owr[1][3], Y.y);
            lgv = reduce2(ups(la0), ups(la1), lane) + obv;
            uint32_t bits = __float_as_uint(lgv);
            uint32_t key = (bits & 0x80000000u) ? ~bits : (bits | 0x80000000u);
            int row = 2 * w + (lane & 1);
            ull cmp = ((ull)key << 8) | (ull)(255 - row);
            ull c1 = __shfl_xor_sync(FULLM, cmp, 1);
            if (c1 > cmp) cmp = c1;
            if (lane == 0) wmax_sh[w] = cmp;
            if (lane < 2) out[(DECL - 1) * NV + row] = lgv;
        }
        __syncthreads();
        if (w == 15) {
            ull v = (lane < 14) ? wmax_sh[lane] : 0ull;
#pragma unroll
            for (int o = 1; o < 32; o <<= 1) {
                ull ot = __shfl_xor_sync(FULLM, v, o);
                if (ot > v) v = ot;
            }
            if (lane == 0)
                out[NV * DECL + (DECL - 1)] = (float)(255 - (int)(v & 0xffu));
        }
        // reset flags for the next graph replay (replays serialize, so safe)
        if (tid < 64) g_flag[tid] = 0;
    }
    cluster_bar();
    (void)out_size; (void)ug;
}

// host-side fork/join resources (created once, on the uncaptured correctness call)
struct HxCtx {
    cudaStream_t s2;
    cudaEvent_t  eF, eJ;
    HxCtx() {
        cudaStreamCreateWithFlags(&s2, cudaStreamNonBlocking);
        cudaEventCreateWithFlags(&eF, cudaEventDisableTiming);
        cudaEventCreateWithFlags(&eJ, cudaEventDisableTiming);
    }
};
static HxCtx& hx_ctx() { static HxCtx c; return c; }

extern "C" void kernel_launch(void* const* d_in, const int* in_sizes, int n_in,
                              void* d_out, int out_size) {
    (void)in_sizes; (void)n_in;
    const int*   data     = (const int*)  d_in[0];
    const int*   data_c   = (const int*)  d_in[1];
    const int*   target_c = (const int*)  d_in[2];
    const float* cond_emb = (const float*)d_in[3];
    const float* enc_emb  = (const float*)d_in[4];
    const float* enc_Wih  = (const float*)d_in[5];
    const float* enc_Whh  = (const float*)d_in[6];
    const float* enc_bih  = (const float*)d_in[7];
    const float* enc_bhh  = (const float*)d_in[8];
    const float* hmu_W    = (const float*)d_in[9];
    const float* hmu_b    = (const float*)d_in[10];
    const float* cmu_W    = (const float*)d_in[11];
    const float* cmu_b    = (const float*)d_in[12];
    const float* fc1_W    = (const float*)d_in[13];
    const float* fc1_b    = (const float*)d_in[14];
    const float* fc2_W    = (const float*)d_in[15];
    const float* fc2_b    = (const float*)d_in[16];
    const float* dec_emb  = (const float*)d_in[17];
    const float* dec_Wih  = (const float*)d_in[18];
    const float* dec_Whh  = (const float*)d_in[19];
    const float* dec_bih  = (const float*)d_in[20];
    const float* dec_bhh  = (const float*)d_in[21];
    const float* out_W    = (const float*)d_in[22];
    const float* out_b    = (const float*)d_in[23];

    HxCtx& c = hx_ctx();

    // fork: table kernel (enc+dec halves in parallel) overlapped with LSTM kernel
    cudaEventRecord(c.eF, 0);
    cudaStreamWaitEvent(c.s2, c.eF, 0);
    table_kernel<<<64, 256, 0, c.s2>>>(data, enc_Wih, enc_bih, enc_bhh, enc_emb,
                                       dec_Wih, dec_bih, dec_bhh, dec_emb);
    cudaEventRecord(c.eJ, c.s2);

    cudaFuncSetAttribute(vae_kernel, cudaFuncAttributeMaxDynamicSharedMemorySize, SMEM_BYTES);
    vae_kernel<<<CS, TPB, SMEM_BYTES>>>(data_c, target_c, cond_emb,
                                        enc_Whh,
                                        hmu_W, hmu_b, cmu_W, cmu_b,
                                        fc1_W, fc1_b, fc2_W, fc2_b,
                                        dec_Whh,
                                        out_W, out_b,
                                        (float*)d_out, out_size);
    cudaStreamWaitEvent(0, c.eJ, 0);
}